// round 12
// baseline (speedup 1.0000x reference)
#include <cuda_runtime.h>
#include <cuda_fp16.h>
#include <cstdint>

#define B_ 16
#define C_ 64
#define H_ 128
#define W_ 128
#define NTOT (B_*C_*H_*W_)
#define NOUT 192
#define WSCALE 16.0f
#define WSCALE_INV 0.0625f

// ---- scratch (allocation-free rule: __device__ globals) ----
__device__ float  g_score[NTOT];
__device__ float  g_gx[NTOT];
__device__ float  g_gy[NTOT];
__device__ __half g_xh16[NTOT];          // NHWC: [b][y][x][ci]
__device__ __half g_xl16[NTOT];
__device__ __half g_B16h[9 * NOUT * 64]; // [tap][n][ci], scaled x16
__device__ __half g_B16l[9 * NOUT * 64];
__device__ float  g_bias[NOUT];

// ---- conv smem layout (halves). M=64 tile -> 2 CTAs/SM ----
#define ARS   72
#define AROWS 66
#define APLN  (AROWS * ARS)               /* 4752 */
#define OFF_AH 0
#define OFF_AL (3 * APLN)                 /* 14256 */
#define OFF_B  (6 * APLN)                 /* 28512 */
#define BTS    (NOUT * ARS)               /* 13824 */
#define SMEM_HALVES (OFF_B + 2 * BTS)     /* 56160 halves = 112320 B */
#define SMEM_BYTES  (SMEM_HALVES * 2)
#define EP_STRIDE 68

__device__ __forceinline__ uint32_t smem_addr(const void* p) {
    return (uint32_t)__cvta_generic_to_shared(p);
}

#define CP_ASYNC16(dst, src) \
    asm volatile("cp.async.cg.shared.global [%0], [%1], 16;" :: "r"(dst), "l"(src) : "memory")
#define CP_COMMIT() asm volatile("cp.async.commit_group;" ::: "memory")
#define CP_WAIT0()  asm volatile("cp.async.wait_group 0;" ::: "memory")
#define CP_WAIT1()  asm volatile("cp.async.wait_group 1;" ::: "memory")

__device__ __forceinline__ void ldsm_x4(uint32_t* r, uint32_t addr) {
    asm volatile("ldmatrix.sync.aligned.m8n8.x4.shared.b16 {%0,%1,%2,%3}, [%4];"
        : "=r"(r[0]), "=r"(r[1]), "=r"(r[2]), "=r"(r[3]) : "r"(addr));
}

__device__ __forceinline__ void mma16(float* d, const uint32_t* a, const uint32_t* b) {
    asm volatile(
        "mma.sync.aligned.m16n8k16.row.col.f32.f16.f16.f32 "
        "{%0,%1,%2,%3}, {%4,%5,%6,%7}, {%8,%9}, {%0,%1,%2,%3};"
        : "+f"(d[0]), "+f"(d[1]), "+f"(d[2]), "+f"(d[3])
        : "r"(a[0]), "r"(a[1]), "r"(a[2]), "r"(a[3]), "r"(b[0]), "r"(b[1]));
}

// ---- split x to fp16 h/l and transpose NCHW -> NHWC ----
__global__ __launch_bounds__(256)
void split_x_kernel(const float* __restrict__ x) {
    __shared__ float tile[64 * 129];
    const int b = blockIdx.x >> 7;
    const int y = blockIdx.x & 127;
    const int tid = threadIdx.x;

    for (int i = 0; i < 32; i++) {
        const int idx = i * 256 + tid;
        const int ci = idx >> 7, xx = idx & 127;
        tile[ci * 129 + xx] = x[(((b * 64 + ci) << 7) + y << 7) + xx];
    }
    __syncthreads();
    for (int i = 0; i < 32; i++) {
        const int idx = i * 256 + tid;
        const int ci = idx & 63, xx = idx >> 6;
        const float v = tile[ci * 129 + xx];
        const __half h = __float2half(v);
        const __half l = __float2half(v - __half2float(h));
        const int o = (((b << 7) + y << 7) + xx << 6) + ci;
        g_xh16[o] = h;
        g_xl16[o] = l;
    }
}

// ---- prep weights: [tap][n][ci], scaled x16, fp16 h/l split ----
__global__ __launch_bounds__(256)
void prep_w_kernel(const float* __restrict__ Ws, const float* __restrict__ bs,
                   const float* __restrict__ Wx, const float* __restrict__ bx,
                   const float* __restrict__ Wy, const float* __restrict__ by) {
    const int idx = blockIdx.x * blockDim.x + threadIdx.x;
    if (idx < 9 * NOUT * 64) {
        const int tap = idx / (NOUT * 64);
        const int rem = idx - tap * (NOUT * 64);
        const int n = rem >> 6, ci = rem & 63;
        const int set = n >> 6, co = n & 63;
        const float* Wt = (set == 0) ? Ws : ((set == 1) ? Wx : Wy);
        const float w = Wt[(co * 64 + ci) * 9 + tap] * WSCALE;
        const __half h = __float2half(w);
        g_B16h[idx] = h;
        g_B16l[idx] = __float2half(w - __half2float(h));
    }
    if (idx < NOUT) {
        const int set = idx >> 6, co = idx & 63;
        const float* Bt = (set == 0) ? bs : ((set == 1) ? bx : by);
        g_bias[idx] = Bt[co];
    }
}

// ---- conv GEMM: CTA = (b, y, x-half). M=64, N=192, K=9x64. 2 CTAs/SM ----
__global__ __launch_bounds__(256, 2)
void conv_mma_kernel() {
    extern __shared__ __half smem[];
    float* s_out = (float*)smem;          // aliases A region in epilogue
    const uint32_t sb = smem_addr(smem);
    const int tid = threadIdx.x;
    const int wid = tid >> 5;
    const int lane = tid & 31;
    const int xh = blockIdx.x & 1;
    const int y = (blockIdx.x >> 1) & 127;
    const int b = blockIdx.x >> 8;
    const int x0 = xh << 6;

    const int mbase = (wid >> 2) * 32;    // 2 m-warps x 32
    const int nbase = (wid & 3) * 48;     // 4 n-warps x 48

    // ldmatrix lane addressing
    const int a_row16 = lane & 15;
    const int a_kh    = (lane >> 4) * 8;
    const int b_ntp   = (lane >> 4) * 8;
    const int b_kh    = ((lane >> 3) & 1) * 8;
    const int b_row   = lane & 7;

    float acc[2][6][4];
    #pragma unroll
    for (int mt = 0; mt < 2; mt++)
        #pragma unroll
        for (int nt = 0; nt < 6; nt++)
            #pragma unroll
            for (int r = 0; r < 4; r++) acc[mt][nt][r] = 0.0f;

    // prefetch one k-half (ci8 range [half*4, half*4+3]) of tap's B (h+l)
    // 768 h-chunks + 768 l-chunks = 1536 / 256 thr = 6 per thread
    #define PREFETCH_HALF(tap_, half_) do {                                      \
        const int gbase_ = (tap_) * NOUT * 64;                                   \
        _Pragma("unroll")                                                        \
        for (int it_ = 0; it_ < 3; it_++) {                                      \
            const int idx_ = it_ * 256 + tid;                                    \
            const int n_ = idx_ >> 2, c8_ = (half_) * 4 + (idx_ & 3);            \
            const int go_ = gbase_ + (n_ << 6) + c8_ * 8;                        \
            const uint32_t so_ = sb + (uint32_t)(OFF_B + n_ * ARS + c8_ * 8) * 2;\
            CP_ASYNC16(so_,           (const char*)&g_B16h[go_]);                \
            CP_ASYNC16(so_ + BTS * 2, (const char*)&g_B16l[go_]);                \
        }                                                                        \
        CP_COMMIT();                                                             \
    } while (0)

    // ---- prologue: prefetch both halves of tap 0 ----
    PREFETCH_HALF(0, 0);
    PREFETCH_HALF(0, 1);

    // ---- stage A: 3 rows (y-1..y+1) x 66 cols (x0-1..x0+64) ----
    #pragma unroll 1
    for (int idx = tid; idx < 3 * AROWS * 8; idx += 256) {
        const int dy = idx / (AROWS * 8);
        const int rem = idx - dy * (AROWS * 8);
        const int xr = rem >> 3;
        const int ci8 = rem & 7;
        const int y_in = y + dy - 1;
        const int x_in = x0 + xr - 1;
        float4 vh = make_float4(0.f, 0.f, 0.f, 0.f);
        float4 vl = vh;
        if ((unsigned)y_in < 128u && (unsigned)x_in < 128u) {
            const int o = ((((b << 7) + y_in << 7) + x_in) << 6) + ci8 * 8;
            vh = *(const float4*)&g_xh16[o];
            vl = *(const float4*)&g_xl16[o];
        }
        const int so = dy * APLN + xr * ARS + ci8 * 8;
        *(float4*)&smem[OFF_AH + so] = vh;
        *(float4*)&smem[OFF_AL + so] = vl;
    }

    #pragma unroll 1
    for (int tap = 0; tap < 9; tap++) {
        const int dy = tap / 3;
        const int dx = tap - dy * 3;

        const uint32_t aBaseH = sb + (uint32_t)(OFF_AH + dy * APLN
                              + (mbase + a_row16 + dx) * ARS + a_kh) * 2;
        const uint32_t aBaseL = aBaseH + (uint32_t)(OFF_AL - OFF_AH) * 2;
        const uint32_t bBaseH = sb + (uint32_t)(OFF_B
                              + (nbase + b_ntp + b_row) * ARS + b_kh) * 2;
        const uint32_t bBaseL = bBaseH + (uint32_t)(BTS) * 2;

        #pragma unroll
        for (int half = 0; half < 2; half++) {
            // wait: this half's data resident (allow 1 newer group in flight)
            if (tap == 8 && half == 1) { CP_WAIT0(); } else { CP_WAIT1(); }
            __syncthreads();

            #pragma unroll
            for (int ks = half * 2; ks < half * 2 + 2; ks++) {
                const uint32_t ko = (uint32_t)ks * 32;
                uint32_t Ah[2][4], Al[2][4], Bh[3][4], Bl[3][4];
                #pragma unroll
                for (int mt = 0; mt < 2; mt++) {
                    ldsm_x4(Ah[mt], aBaseH + (uint32_t)(mt * 16 * ARS) * 2 + ko);
                    ldsm_x4(Al[mt], aBaseL + (uint32_t)(mt * 16 * ARS) * 2 + ko);
                }
                #pragma unroll
                for (int p = 0; p < 3; p++) {
                    ldsm_x4(Bh[p], bBaseH + (uint32_t)(p * 16 * ARS) * 2 + ko);
                    ldsm_x4(Bl[p], bBaseL + (uint32_t)(p * 16 * ARS) * 2 + ko);
                }
                #pragma unroll
                for (int mt = 0; mt < 2; mt++)
                    #pragma unroll
                    for (int nt = 0; nt < 6; nt++)
                        mma16(acc[mt][nt], Ah[mt], &Bh[nt >> 1][(nt & 1) * 2]);
                #pragma unroll
                for (int mt = 0; mt < 2; mt++)
                    #pragma unroll
                    for (int nt = 0; nt < 6; nt++)
                        mma16(acc[mt][nt], Ah[mt], &Bl[nt >> 1][(nt & 1) * 2]);
                #pragma unroll
                for (int mt = 0; mt < 2; mt++)
                    #pragma unroll
                    for (int nt = 0; nt < 6; nt++)
                        mma16(acc[mt][nt], Al[mt], &Bh[nt >> 1][(nt & 1) * 2]);
            }

            __syncthreads();   // all warps done reading this half's columns
            if (tap < 8) PREFETCH_HALF(tap + 1, half);   // overlaps next half's mma
        }
    }

    __syncthreads();            // A region dead; safe to alias as s_out

    // ---- epilogue: transpose through smem, coalesced float4 stores ----
    const int lr = lane >> 2;
    const int lc = lane & 3;
    #pragma unroll
    for (int nt = 0; nt < 6; nt++) {
        const int n0 = nbase + nt * 8 + 2 * lc;
        #pragma unroll
        for (int mt = 0; mt < 2; mt++) {
            const int m0 = mbase + mt * 16 + lr;
            s_out[n0 * EP_STRIDE + m0]           = acc[mt][nt][0];
            s_out[(n0 + 1) * EP_STRIDE + m0]     = acc[mt][nt][1];
            s_out[n0 * EP_STRIDE + m0 + 8]       = acc[mt][nt][2];
            s_out[(n0 + 1) * EP_STRIDE + m0 + 8] = acc[mt][nt][3];
        }
    }
    __syncthreads();

    // readout: 192 rows x 16 float4, coalesced
    #pragma unroll 1
    for (int it = 0; it < 12; it++) {
        const int idx = it * 256 + tid;
        const int n = idx >> 4;
        const int m4 = idx & 15;
        const int set = n >> 6, co = n & 63;
        float* op = (set == 0) ? g_score : ((set == 1) ? g_gx : g_gy);
        const float bias = __ldg(&g_bias[n]);
        float4 v = *(const float4*)&s_out[n * EP_STRIDE + m4 * 4];
        v.x = fmaf(v.x, WSCALE_INV, bias);
        v.y = fmaf(v.y, WSCALE_INV, bias);
        v.z = fmaf(v.z, WSCALE_INV, bias);
        v.w = fmaf(v.w, WSCALE_INV, bias);
        *(float4*)&op[((b * 64 + co) << 14) + (y << 7) + x0 + m4 * 4] = v;
    }
}

// ---- bilinear grid sample, 4 px/thread (align_corners=False, zeros) ----
__global__ void sample_kernel(float* __restrict__ out) {
    const int i4 = (blockIdx.x * blockDim.x + threadIdx.x) * 4;
    if (i4 >= NTOT) return;
    const int n = i4 >> 14;
    const float* img = g_score + ((size_t)n << 14);
    const float4 gx4 = *(const float4*)&g_gx[i4];
    const float4 gy4 = *(const float4*)&g_gy[i4];
    float r[4];
    const float gxs[4] = {gx4.x, gx4.y, gx4.z, gx4.w};
    const float gys[4] = {gy4.x, gy4.y, gy4.z, gy4.w};
    #pragma unroll
    for (int j = 0; j < 4; j++) {
        const float ix = ((gxs[j] + 1.0f) * (float)W_ - 1.0f) * 0.5f;
        const float iy = ((gys[j] + 1.0f) * (float)H_ - 1.0f) * 0.5f;
        const float x0f = floorf(ix);
        const float y0f = floorf(iy);
        const int ix0 = (int)x0f, iy0 = (int)y0f;
        const int ix1 = ix0 + 1, iy1 = iy0 + 1;
        const float wx1 = ix - x0f, wy1 = iy - y0f;
        const float wx0 = 1.0f - wx1, wy0 = 1.0f - wy1;
        float v = 0.0f;
        if ((unsigned)iy0 < H_ && (unsigned)ix0 < W_) v = fmaf(__ldg(&img[iy0 * W_ + ix0]), wy0 * wx0, v);
        if ((unsigned)iy0 < H_ && (unsigned)ix1 < W_) v = fmaf(__ldg(&img[iy0 * W_ + ix1]), wy0 * wx1, v);
        if ((unsigned)iy1 < H_ && (unsigned)ix0 < W_) v = fmaf(__ldg(&img[iy1 * W_ + ix0]), wy1 * wx0, v);
        if ((unsigned)iy1 < H_ && (unsigned)ix1 < W_) v = fmaf(__ldg(&img[iy1 * W_ + ix1]), wy1 * wx1, v);
        r[j] = v;
    }
    *(float4*)&out[i4] = make_float4(r[0], r[1], r[2], r[3]);
}

extern "C" void kernel_launch(void* const* d_in, const int* in_sizes, int n_in,
                              void* d_out, int out_size) {
    const float* x  = (const float*)d_in[0];
    const float* Ws = (const float*)d_in[1];
    const float* bs = (const float*)d_in[2];
    const float* Wx = (const float*)d_in[3];
    const float* bx = (const float*)d_in[4];
    const float* Wy = (const float*)d_in[5];
    const float* by = (const float*)d_in[6];
    float* out = (float*)d_out;

    cudaFuncSetAttribute(conv_mma_kernel,
                         cudaFuncAttributeMaxDynamicSharedMemorySize, SMEM_BYTES);

    split_x_kernel<<<B_ * H_, 256>>>(x);
    prep_w_kernel<<<(9 * NOUT * 64 + 255) / 256, 256>>>(Ws, bs, Wx, bx, Wy, by);
    conv_mma_kernel<<<B_ * H_ * 2, 256, SMEM_BYTES>>>();
    sample_kernel<<<NTOT / 4 / 256, 256>>>(out);
}

// round 13
// speedup vs baseline: 1.0774x; 1.0774x over previous
#include <cuda_runtime.h>
#include <cuda_fp16.h>
#include <cstdint>

#define B_ 16
#define C_ 64
#define H_ 128
#define W_ 128
#define NTOT (B_*C_*H_*W_)
#define NOUT 192
#define WSCALE 16.0f
#define WSCALE_INV 0.0625f

// ---- scratch (allocation-free rule: __device__ globals) ----
__device__ float  g_score[NTOT];
__device__ float  g_gx[NTOT];
__device__ float  g_gy[NTOT];
__device__ __half g_xh16[NTOT];          // NHWC: [b][y][x][ci]
__device__ __half g_xl16[NTOT];
__device__ __half g_B16h[9 * NOUT * 64]; // [tap][n][ci], scaled x16
__device__ __half g_B16l[9 * NOUT * 64];
__device__ float  g_bias[NOUT];

// ---- conv smem layout (halves). M=64 tile -> 2 CTAs/SM ----
#define ARS   72
#define AROWS 66
#define APLN  (AROWS * ARS)               /* 4752 */
#define OFF_AH 0
#define OFF_AL (3 * APLN)                 /* 14256 */
#define OFF_B  (6 * APLN)                 /* 28512 */
#define BTS    (NOUT * ARS)               /* 13824 */
#define SMEM_HALVES (OFF_B + 2 * BTS)     /* 56160 halves = 112320 B */
#define SMEM_BYTES  (SMEM_HALVES * 2)
#define EP_STRIDE 68

__device__ __forceinline__ uint32_t smem_addr(const void* p) {
    return (uint32_t)__cvta_generic_to_shared(p);
}

#define CP_ASYNC16(dst, src) \
    asm volatile("cp.async.cg.shared.global [%0], [%1], 16;" :: "r"(dst), "l"(src) : "memory")
#define CP_ASYNC16Z(dst, src, sz) \
    asm volatile("cp.async.cg.shared.global [%0], [%1], 16, %2;" :: "r"(dst), "l"(src), "r"(sz) : "memory")
#define CP_COMMIT() asm volatile("cp.async.commit_group;" ::: "memory")
#define CP_WAIT0()  asm volatile("cp.async.wait_group 0;" ::: "memory")

__device__ __forceinline__ void ldsm_x4(uint32_t* r, uint32_t addr) {
    asm volatile("ldmatrix.sync.aligned.m8n8.x4.shared.b16 {%0,%1,%2,%3}, [%4];"
        : "=r"(r[0]), "=r"(r[1]), "=r"(r[2]), "=r"(r[3]) : "r"(addr));
}

__device__ __forceinline__ void mma16(float* d, const uint32_t* a, const uint32_t* b) {
    asm volatile(
        "mma.sync.aligned.m16n8k16.row.col.f32.f16.f16.f32 "
        "{%0,%1,%2,%3}, {%4,%5,%6,%7}, {%8,%9}, {%0,%1,%2,%3};"
        : "+f"(d[0]), "+f"(d[1]), "+f"(d[2]), "+f"(d[3])
        : "r"(a[0]), "r"(a[1]), "r"(a[2]), "r"(a[3]), "r"(b[0]), "r"(b[1]));
}

// ---- split x to fp16 h/l and transpose NCHW -> NHWC ----
__global__ __launch_bounds__(256)
void split_x_kernel(const float* __restrict__ x) {
    __shared__ float tile[64 * 129];
    const int b = blockIdx.x >> 7;
    const int y = blockIdx.x & 127;
    const int tid = threadIdx.x;

    for (int i = 0; i < 32; i++) {
        const int idx = i * 256 + tid;
        const int ci = idx >> 7, xx = idx & 127;
        tile[ci * 129 + xx] = x[(((b * 64 + ci) << 7) + y << 7) + xx];
    }
    __syncthreads();
    for (int i = 0; i < 32; i++) {
        const int idx = i * 256 + tid;
        const int ci = idx & 63, xx = idx >> 6;
        const float v = tile[ci * 129 + xx];
        const __half h = __float2half(v);
        const __half l = __float2half(v - __half2float(h));
        const int o = (((b << 7) + y << 7) + xx << 6) + ci;
        g_xh16[o] = h;
        g_xl16[o] = l;
    }
}

// ---- prep weights: [tap][n][ci], scaled x16, fp16 h/l split ----
__global__ __launch_bounds__(256)
void prep_w_kernel(const float* __restrict__ Ws, const float* __restrict__ bs,
                   const float* __restrict__ Wx, const float* __restrict__ bx,
                   const float* __restrict__ Wy, const float* __restrict__ by) {
    const int idx = blockIdx.x * blockDim.x + threadIdx.x;
    if (idx < 9 * NOUT * 64) {
        const int tap = idx / (NOUT * 64);
        const int rem = idx - tap * (NOUT * 64);
        const int n = rem >> 6, ci = rem & 63;
        const int set = n >> 6, co = n & 63;
        const float* Wt = (set == 0) ? Ws : ((set == 1) ? Wx : Wy);
        const float w = Wt[(co * 64 + ci) * 9 + tap] * WSCALE;
        const __half h = __float2half(w);
        g_B16h[idx] = h;
        g_B16l[idx] = __float2half(w - __half2float(h));
    }
    if (idx < NOUT) {
        const int set = idx >> 6, co = idx & 63;
        const float* Bt = (set == 0) ? bs : ((set == 1) ? bx : by);
        g_bias[idx] = Bt[co];
    }
}

// ---- conv GEMM: CTA = (b, y, x-half). M=64, N=192, K=9x64. 2 CTAs/SM ----
__global__ __launch_bounds__(256, 2)
void conv_mma_kernel() {
    extern __shared__ __half smem[];
    float* s_out = (float*)smem;          // aliases A region in epilogue
    const uint32_t sb = smem_addr(smem);
    const int tid = threadIdx.x;
    const int wid = tid >> 5;
    const int lane = tid & 31;
    const int xh = blockIdx.x & 1;
    const int y = (blockIdx.x >> 1) & 127;
    const int b = blockIdx.x >> 8;
    const int x0 = xh << 6;

    const int mbase = (wid >> 2) * 32;    // 2 m-warps x 32
    const int nbase = (wid & 3) * 48;     // 4 n-warps x 48

    // ldmatrix lane addressing
    const int a_row16 = lane & 15;
    const int a_kh    = (lane >> 4) * 8;
    const int b_ntp   = (lane >> 4) * 8;
    const int b_kh    = ((lane >> 3) & 1) * 8;
    const int b_row   = lane & 7;

    float acc[2][6][4];
    #pragma unroll
    for (int mt = 0; mt < 2; mt++)
        #pragma unroll
        for (int nt = 0; nt < 6; nt++)
            #pragma unroll
            for (int r = 0; r < 4; r++) acc[mt][nt][r] = 0.0f;

    // ---- prefetch B tap 0 via cp.async ----
    #pragma unroll
    for (int it = 0; it < 6; it++) {
        const int idx = it * 256 + tid;
        const int n = idx >> 3, ci8 = idx & 7;
        const int go = (n << 6) + ci8 * 8;
        const uint32_t so = sb + (uint32_t)(OFF_B + n * ARS + ci8 * 8) * 2;
        CP_ASYNC16(so,           (const char*)&g_B16h[go]);
        CP_ASYNC16(so + BTS * 2, (const char*)&g_B16l[go]);
    }

    // ---- stage A via cp.async (zero-fill for halo): 3 rows x 66 cols ----
    #pragma unroll
    for (int it = 0; it < 7; it++) {
        const int idx = it * 256 + tid;
        if (idx < 3 * AROWS * 8) {
            const int dy = idx / (AROWS * 8);
            const int rem = idx - dy * (AROWS * 8);
            const int xr = rem >> 3;
            const int ci8 = rem & 7;
            const int y_in = y + dy - 1;
            const int x_in = x0 + xr - 1;
            const bool ok = ((unsigned)y_in < 128u) & ((unsigned)x_in < 128u);
            const int yc = ok ? y_in : 0, xc = ok ? x_in : 0;
            const int o = ((((b << 7) + yc << 7) + xc) << 6) + ci8 * 8;
            const uint32_t sz = ok ? 16u : 0u;
            const uint32_t so = sb + (uint32_t)(OFF_AH + dy * APLN + xr * ARS + ci8 * 8) * 2;
            CP_ASYNC16Z(so,                           (const char*)&g_xh16[o], sz);
            CP_ASYNC16Z(so + (OFF_AL - OFF_AH) * 2,   (const char*)&g_xl16[o], sz);
        }
    }
    CP_COMMIT();
    CP_WAIT0();
    __syncthreads();

    #pragma unroll 1
    for (int tap = 0; tap < 9; tap++) {
        const int dy = tap / 3;
        const int dx = tap - dy * 3;

        const uint32_t aBaseH = sb + (uint32_t)(OFF_AH + dy * APLN
                              + (mbase + a_row16 + dx) * ARS + a_kh) * 2;
        const uint32_t aBaseL = aBaseH + (uint32_t)(OFF_AL - OFF_AH) * 2;
        const uint32_t bBaseH = sb + (uint32_t)(OFF_B
                              + (nbase + b_ntp + b_row) * ARS + b_kh) * 2;
        const uint32_t bBaseL = bBaseH + (uint32_t)(BTS) * 2;

        #pragma unroll
        for (int ks = 0; ks < 4; ks++) {
            const uint32_t ko = (uint32_t)ks * 32;
            uint32_t Ah[2][4], Al[2][4], Bh[3][4], Bl[3][4];
            #pragma unroll
            for (int mt = 0; mt < 2; mt++) {
                ldsm_x4(Ah[mt], aBaseH + (uint32_t)(mt * 16 * ARS) * 2 + ko);
                ldsm_x4(Al[mt], aBaseL + (uint32_t)(mt * 16 * ARS) * 2 + ko);
            }
            #pragma unroll
            for (int p = 0; p < 3; p++) {
                ldsm_x4(Bh[p], bBaseH + (uint32_t)(p * 16 * ARS) * 2 + ko);
                ldsm_x4(Bl[p], bBaseL + (uint32_t)(p * 16 * ARS) * 2 + ko);
            }
            #pragma unroll
            for (int mt = 0; mt < 2; mt++)
                #pragma unroll
                for (int nt = 0; nt < 6; nt++)
                    mma16(acc[mt][nt], Ah[mt], &Bh[nt >> 1][(nt & 1) * 2]);
            #pragma unroll
            for (int mt = 0; mt < 2; mt++)
                #pragma unroll
                for (int nt = 0; nt < 6; nt++)
                    mma16(acc[mt][nt], Ah[mt], &Bl[nt >> 1][(nt & 1) * 2]);
            #pragma unroll
            for (int mt = 0; mt < 2; mt++)
                #pragma unroll
                for (int nt = 0; nt < 6; nt++)
                    mma16(acc[mt][nt], Al[mt], &Bh[nt >> 1][(nt & 1) * 2]);
        }

        // single-buffered B: reload for next tap (bubble hidden by co-CTA)
        if (tap < 8) {
            __syncthreads();    // all warps done reading B
            const int gbase = (tap + 1) * NOUT * 64;
            #pragma unroll
            for (int it = 0; it < 6; it++) {
                const int idx = it * 256 + tid;
                const int n = idx >> 3, ci8 = idx & 7;
                const int go = gbase + (n << 6) + ci8 * 8;
                const uint32_t so = sb + (uint32_t)(OFF_B + n * ARS + ci8 * 8) * 2;
                CP_ASYNC16(so,           (const char*)&g_B16h[go]);
                CP_ASYNC16(so + BTS * 2, (const char*)&g_B16l[go]);
            }
            CP_COMMIT();
            CP_WAIT0();
            __syncthreads();    // B visible to all
        }
    }

    __syncthreads();            // A region dead; safe to alias as s_out

    // ---- epilogue: transpose through smem, coalesced float4 stores ----
    const int lr = lane >> 2;
    const int lc = lane & 3;
    #pragma unroll
    for (int nt = 0; nt < 6; nt++) {
        const int n0 = nbase + nt * 8 + 2 * lc;
        #pragma unroll
        for (int mt = 0; mt < 2; mt++) {
            const int m0 = mbase + mt * 16 + lr;
            s_out[n0 * EP_STRIDE + m0]           = acc[mt][nt][0];
            s_out[(n0 + 1) * EP_STRIDE + m0]     = acc[mt][nt][1];
            s_out[n0 * EP_STRIDE + m0 + 8]       = acc[mt][nt][2];
            s_out[(n0 + 1) * EP_STRIDE + m0 + 8] = acc[mt][nt][3];
        }
    }
    __syncthreads();

    // readout: 192 rows x 16 float4, coalesced
    #pragma unroll 1
    for (int it = 0; it < 12; it++) {
        const int idx = it * 256 + tid;
        const int n = idx >> 4;
        const int m4 = idx & 15;
        const int set = n >> 6, co = n & 63;
        float* op = (set == 0) ? g_score : ((set == 1) ? g_gx : g_gy);
        const float bias = __ldg(&g_bias[n]);
        float4 v = *(const float4*)&s_out[n * EP_STRIDE + m4 * 4];
        v.x = fmaf(v.x, WSCALE_INV, bias);
        v.y = fmaf(v.y, WSCALE_INV, bias);
        v.z = fmaf(v.z, WSCALE_INV, bias);
        v.w = fmaf(v.w, WSCALE_INV, bias);
        *(float4*)&op[((b * 64 + co) << 14) + (y << 7) + x0 + m4 * 4] = v;
    }
}

// ---- bilinear grid sample, 8 px/thread (align_corners=False, zeros) ----
__global__ void sample_kernel(float* __restrict__ out) {
    const int i8 = (blockIdx.x * blockDim.x + threadIdx.x) * 8;
    if (i8 >= NTOT) return;
    const int n = i8 >> 14;
    const float* img = g_score + ((size_t)n << 14);

    #pragma unroll
    for (int q = 0; q < 2; q++) {
        const int i4 = i8 + q * 4;
        const float4 gx4 = *(const float4*)&g_gx[i4];
        const float4 gy4 = *(const float4*)&g_gy[i4];
        float r[4];
        const float gxs[4] = {gx4.x, gx4.y, gx4.z, gx4.w};
        const float gys[4] = {gy4.x, gy4.y, gy4.z, gy4.w};
        #pragma unroll
        for (int j = 0; j < 4; j++) {
            const float ix = ((gxs[j] + 1.0f) * (float)W_ - 1.0f) * 0.5f;
            const float iy = ((gys[j] + 1.0f) * (float)H_ - 1.0f) * 0.5f;
            const float x0f = floorf(ix);
            const float y0f = floorf(iy);
            const int ix0 = (int)x0f, iy0 = (int)y0f;
            const int ix1 = ix0 + 1, iy1 = iy0 + 1;
            const float wx1 = ix - x0f, wy1 = iy - y0f;
            const float wx0 = 1.0f - wx1, wy0 = 1.0f - wy1;
            float v = 0.0f;
            if ((unsigned)iy0 < H_ && (unsigned)ix0 < W_) v = fmaf(__ldg(&img[iy0 * W_ + ix0]), wy0 * wx0, v);
            if ((unsigned)iy0 < H_ && (unsigned)ix1 < W_) v = fmaf(__ldg(&img[iy0 * W_ + ix1]), wy0 * wx1, v);
            if ((unsigned)iy1 < H_ && (unsigned)ix0 < W_) v = fmaf(__ldg(&img[iy1 * W_ + ix0]), wy1 * wx0, v);
            if ((unsigned)iy1 < H_ && (unsigned)ix1 < W_) v = fmaf(__ldg(&img[iy1 * W_ + ix1]), wy1 * wx1, v);
            r[j] = v;
        }
        *(float4*)&out[i4] = make_float4(r[0], r[1], r[2], r[3]);
    }
}

extern "C" void kernel_launch(void* const* d_in, const int* in_sizes, int n_in,
                              void* d_out, int out_size) {
    const float* x  = (const float*)d_in[0];
    const float* Ws = (const float*)d_in[1];
    const float* bs = (const float*)d_in[2];
    const float* Wx = (const float*)d_in[3];
    const float* bx = (const float*)d_in[4];
    const float* Wy = (const float*)d_in[5];
    const float* by = (const float*)d_in[6];
    float* out = (float*)d_out;

    cudaFuncSetAttribute(conv_mma_kernel,
                         cudaFuncAttributeMaxDynamicSharedMemorySize, SMEM_BYTES);

    split_x_kernel<<<B_ * H_, 256>>>(x);
    prep_w_kernel<<<(9 * NOUT * 64 + 255) / 256, 256>>>(Ws, bs, Wx, bx, Wy, by);
    conv_mma_kernel<<<B_ * H_ * 2, 256, SMEM_BYTES>>>();
    sample_kernel<<<NTOT / 8 / 256, 256>>>(out);
}

// round 14
// speedup vs baseline: 1.1071x; 1.0276x over previous
#include <cuda_runtime.h>
#include <cuda_fp16.h>
#include <cstdint>

#define B_ 16
#define C_ 64
#define H_ 128
#define W_ 128
#define NTOT (B_*C_*H_*W_)
#define NOUT 192
#define WSCALE 16.0f
#define WSCALE_INV 0.0625f

// ---- scratch (allocation-free rule: __device__ globals) ----
__device__ float  g_score[NTOT];
__device__ float  g_gx[NTOT];
__device__ float  g_gy[NTOT];
__device__ __half g_xh16[NTOT];          // NHWC: [b][y][x][ci]
__device__ __half g_xl16[NTOT];
__device__ __half g_B16h[9 * NOUT * 64]; // [tap][n][ci], scaled x16
__device__ __half g_B16l[9 * NOUT * 64];
__device__ float  g_bias[NOUT];

// ---- conv smem layout (halves). M=64 tile -> 2 CTAs/SM ----
#define ARS   72
#define AROWS 66
#define APLN  (AROWS * ARS)               /* 4752 */
#define OFF_AH 0
#define OFF_AL (3 * APLN)                 /* 14256 */
#define OFF_B  (6 * APLN)                 /* 28512 */
#define BTS    (NOUT * ARS)               /* 13824 */
#define SMEM_HALVES (OFF_B + 2 * BTS)     /* 56160 halves = 112320 B */
#define SMEM_BYTES  (SMEM_HALVES * 2)
#define EP_STRIDE 68

__device__ __forceinline__ uint32_t smem_addr(const void* p) {
    return (uint32_t)__cvta_generic_to_shared(p);
}

#define CP_ASYNC16(dst, src) \
    asm volatile("cp.async.cg.shared.global [%0], [%1], 16;" :: "r"(dst), "l"(src) : "memory")
#define CP_ASYNC16Z(dst, src, sz) \
    asm volatile("cp.async.cg.shared.global [%0], [%1], 16, %2;" :: "r"(dst), "l"(src), "r"(sz) : "memory")
#define CP_COMMIT() asm volatile("cp.async.commit_group;" ::: "memory")
#define CP_WAIT0()  asm volatile("cp.async.wait_group 0;" ::: "memory")

__device__ __forceinline__ void ldsm_x4(uint32_t* r, uint32_t addr) {
    asm volatile("ldmatrix.sync.aligned.m8n8.x4.shared.b16 {%0,%1,%2,%3}, [%4];"
        : "=r"(r[0]), "=r"(r[1]), "=r"(r[2]), "=r"(r[3]) : "r"(addr));
}

__device__ __forceinline__ void mma16(float* d, const uint32_t* a, const uint32_t* b) {
    asm volatile(
        "mma.sync.aligned.m16n8k16.row.col.f32.f16.f16.f32 "
        "{%0,%1,%2,%3}, {%4,%5,%6,%7}, {%8,%9}, {%0,%1,%2,%3};"
        : "+f"(d[0]), "+f"(d[1]), "+f"(d[2]), "+f"(d[3])
        : "r"(a[0]), "r"(a[1]), "r"(a[2]), "r"(a[3]), "r"(b[0]), "r"(b[1]));
}

// ---- split x to fp16 h/l and transpose NCHW -> NHWC ----
__global__ __launch_bounds__(256)
void split_x_kernel(const float* __restrict__ x) {
    __shared__ float tile[64 * 129];
    const int b = blockIdx.x >> 7;
    const int y = blockIdx.x & 127;
    const int tid = threadIdx.x;

    for (int i = 0; i < 32; i++) {
        const int idx = i * 256 + tid;
        const int ci = idx >> 7, xx = idx & 127;
        tile[ci * 129 + xx] = x[(((b * 64 + ci) << 7) + y << 7) + xx];
    }
    __syncthreads();
    for (int i = 0; i < 32; i++) {
        const int idx = i * 256 + tid;
        const int ci = idx & 63, xx = idx >> 6;
        const float v = tile[ci * 129 + xx];
        const __half h = __float2half(v);
        const __half l = __float2half(v - __half2float(h));
        const int o = (((b << 7) + y << 7) + xx << 6) + ci;
        g_xh16[o] = h;
        g_xl16[o] = l;
    }
}

// ---- prep weights: [tap][n][ci], scaled x16, fp16 h/l split ----
__global__ __launch_bounds__(256)
void prep_w_kernel(const float* __restrict__ Ws, const float* __restrict__ bs,
                   const float* __restrict__ Wx, const float* __restrict__ bx,
                   const float* __restrict__ Wy, const float* __restrict__ by) {
    const int idx = blockIdx.x * blockDim.x + threadIdx.x;
    if (idx < 9 * NOUT * 64) {
        const int tap = idx / (NOUT * 64);
        const int rem = idx - tap * (NOUT * 64);
        const int n = rem >> 6, ci = rem & 63;
        const int set = n >> 6, co = n & 63;
        const float* Wt = (set == 0) ? Ws : ((set == 1) ? Wx : Wy);
        const float w = Wt[(co * 64 + ci) * 9 + tap] * WSCALE;
        const __half h = __float2half(w);
        g_B16h[idx] = h;
        g_B16l[idx] = __float2half(w - __half2float(h));
    }
    if (idx < NOUT) {
        const int set = idx >> 6, co = idx & 63;
        const float* Bt = (set == 0) ? bs : ((set == 1) ? bx : by);
        g_bias[idx] = Bt[co];
    }
}

// ---- conv GEMM: CTA = (b, y, x-half). M=64, N=192, K=9x64. 2 CTAs/SM ----
// Tap order rotated by blockIdx.x % 9 so co-resident CTAs de-phase their
// per-tap B-reload bubbles (148 mod 9 = 4 != 0).
__global__ __launch_bounds__(256, 2)
void conv_mma_kernel() {
    extern __shared__ __half smem[];
    float* s_out = (float*)smem;          // aliases A region in epilogue
    const uint32_t sb = smem_addr(smem);
    const int tid = threadIdx.x;
    const int wid = tid >> 5;
    const int lane = tid & 31;
    const int xh = blockIdx.x & 1;
    const int y = (blockIdx.x >> 1) & 127;
    const int b = blockIdx.x >> 8;
    const int x0 = xh << 6;
    const int toff = blockIdx.x % 9;

    const int mbase = (wid >> 2) * 32;    // 2 m-warps x 32
    const int nbase = (wid & 3) * 48;     // 4 n-warps x 48

    // ldmatrix lane addressing
    const int a_row16 = lane & 15;
    const int a_kh    = (lane >> 4) * 8;
    const int b_ntp   = (lane >> 4) * 8;
    const int b_kh    = ((lane >> 3) & 1) * 8;
    const int b_row   = lane & 7;

    float acc[2][6][4];
    #pragma unroll
    for (int mt = 0; mt < 2; mt++)
        #pragma unroll
        for (int nt = 0; nt < 6; nt++)
            #pragma unroll
            for (int r = 0; r < 4; r++) acc[mt][nt][r] = 0.0f;

    // ---- prefetch B for first tap (= toff) via cp.async ----
    {
        const int gbase = toff * NOUT * 64;
        #pragma unroll
        for (int it = 0; it < 6; it++) {
            const int idx = it * 256 + tid;
            const int n = idx >> 3, ci8 = idx & 7;
            const int go = gbase + (n << 6) + ci8 * 8;
            const uint32_t so = sb + (uint32_t)(OFF_B + n * ARS + ci8 * 8) * 2;
            CP_ASYNC16(so,           (const char*)&g_B16h[go]);
            CP_ASYNC16(so + BTS * 2, (const char*)&g_B16l[go]);
        }
    }

    // ---- stage A via cp.async (zero-fill for halo): 3 rows x 66 cols ----
    #pragma unroll
    for (int it = 0; it < 7; it++) {
        const int idx = it * 256 + tid;
        if (idx < 3 * AROWS * 8) {
            const int dy = idx / (AROWS * 8);
            const int rem = idx - dy * (AROWS * 8);
            const int xr = rem >> 3;
            const int ci8 = rem & 7;
            const int y_in = y + dy - 1;
            const int x_in = x0 + xr - 1;
            const bool ok = ((unsigned)y_in < 128u) & ((unsigned)x_in < 128u);
            const int yc = ok ? y_in : 0, xc = ok ? x_in : 0;
            const int o = ((((b << 7) + yc << 7) + xc) << 6) + ci8 * 8;
            const uint32_t sz = ok ? 16u : 0u;
            const uint32_t so = sb + (uint32_t)(OFF_AH + dy * APLN + xr * ARS + ci8 * 8) * 2;
            CP_ASYNC16Z(so,                           (const char*)&g_xh16[o], sz);
            CP_ASYNC16Z(so + (OFF_AL - OFF_AH) * 2,   (const char*)&g_xl16[o], sz);
        }
    }
    CP_COMMIT();
    CP_WAIT0();
    __syncthreads();

    #pragma unroll 1
    for (int t = 0; t < 9; t++) {
        int tap = t + toff; if (tap >= 9) tap -= 9;
        const int dy = tap / 3;
        const int dx = tap - dy * 3;

        const uint32_t aBaseH = sb + (uint32_t)(OFF_AH + dy * APLN
                              + (mbase + a_row16 + dx) * ARS + a_kh) * 2;
        const uint32_t aBaseL = aBaseH + (uint32_t)(OFF_AL - OFF_AH) * 2;
        const uint32_t bBaseH = sb + (uint32_t)(OFF_B
                              + (nbase + b_ntp + b_row) * ARS + b_kh) * 2;
        const uint32_t bBaseL = bBaseH + (uint32_t)(BTS) * 2;

        #pragma unroll
        for (int ks = 0; ks < 4; ks++) {
            const uint32_t ko = (uint32_t)ks * 32;
            uint32_t Ah[2][4], Al[2][4], Bh[3][4], Bl[3][4];
            #pragma unroll
            for (int mt = 0; mt < 2; mt++) {
                ldsm_x4(Ah[mt], aBaseH + (uint32_t)(mt * 16 * ARS) * 2 + ko);
                ldsm_x4(Al[mt], aBaseL + (uint32_t)(mt * 16 * ARS) * 2 + ko);
            }
            #pragma unroll
            for (int p = 0; p < 3; p++) {
                ldsm_x4(Bh[p], bBaseH + (uint32_t)(p * 16 * ARS) * 2 + ko);
                ldsm_x4(Bl[p], bBaseL + (uint32_t)(p * 16 * ARS) * 2 + ko);
            }
            #pragma unroll
            for (int mt = 0; mt < 2; mt++)
                #pragma unroll
                for (int nt = 0; nt < 6; nt++)
                    mma16(acc[mt][nt], Ah[mt], &Bh[nt >> 1][(nt & 1) * 2]);
            #pragma unroll
            for (int mt = 0; mt < 2; mt++)
                #pragma unroll
                for (int nt = 0; nt < 6; nt++)
                    mma16(acc[mt][nt], Ah[mt], &Bl[nt >> 1][(nt & 1) * 2]);
            #pragma unroll
            for (int mt = 0; mt < 2; mt++)
                #pragma unroll
                for (int nt = 0; nt < 6; nt++)
                    mma16(acc[mt][nt], Al[mt], &Bh[nt >> 1][(nt & 1) * 2]);
        }

        // single-buffered B: reload for next tap (bubble covered by de-phased co-CTA)
        if (t < 8) {
            __syncthreads();    // all warps done reading B
            int tapn = t + 1 + toff; if (tapn >= 9) tapn -= 9;
            const int gbase = tapn * NOUT * 64;
            #pragma unroll
            for (int it = 0; it < 6; it++) {
                const int idx = it * 256 + tid;
                const int n = idx >> 3, ci8 = idx & 7;
                const int go = gbase + (n << 6) + ci8 * 8;
                const uint32_t so = sb + (uint32_t)(OFF_B + n * ARS + ci8 * 8) * 2;
                CP_ASYNC16(so,           (const char*)&g_B16h[go]);
                CP_ASYNC16(so + BTS * 2, (const char*)&g_B16l[go]);
            }
            CP_COMMIT();
            CP_WAIT0();
            __syncthreads();    // B visible to all
        }
    }

    __syncthreads();            // A region dead; safe to alias as s_out

    // ---- epilogue: transpose through smem, coalesced float4 stores ----
    const int lr = lane >> 2;
    const int lc = lane & 3;
    #pragma unroll
    for (int nt = 0; nt < 6; nt++) {
        const int n0 = nbase + nt * 8 + 2 * lc;
        #pragma unroll
        for (int mt = 0; mt < 2; mt++) {
            const int m0 = mbase + mt * 16 + lr;
            s_out[n0 * EP_STRIDE + m0]           = acc[mt][nt][0];
            s_out[(n0 + 1) * EP_STRIDE + m0]     = acc[mt][nt][1];
            s_out[n0 * EP_STRIDE + m0 + 8]       = acc[mt][nt][2];
            s_out[(n0 + 1) * EP_STRIDE + m0 + 8] = acc[mt][nt][3];
        }
    }
    __syncthreads();

    // readout: 192 rows x 16 float4, coalesced
    #pragma unroll 1
    for (int it = 0; it < 12; it++) {
        const int idx = it * 256 + tid;
        const int n = idx >> 4;
        const int m4 = idx & 15;
        const int set = n >> 6, co = n & 63;
        float* op = (set == 0) ? g_score : ((set == 1) ? g_gx : g_gy);
        const float bias = __ldg(&g_bias[n]);
        float4 v = *(const float4*)&s_out[n * EP_STRIDE + m4 * 4];
        v.x = fmaf(v.x, WSCALE_INV, bias);
        v.y = fmaf(v.y, WSCALE_INV, bias);
        v.z = fmaf(v.z, WSCALE_INV, bias);
        v.w = fmaf(v.w, WSCALE_INV, bias);
        *(float4*)&op[((b * 64 + co) << 14) + (y << 7) + x0 + m4 * 4] = v;
    }
}

// ---- bilinear grid sample, 4 px/thread (align_corners=False, zeros) ----
__global__ void sample_kernel(float* __restrict__ out) {
    const int i4 = (blockIdx.x * blockDim.x + threadIdx.x) * 4;
    if (i4 >= NTOT) return;
    const int n = i4 >> 14;
    const float* img = g_score + ((size_t)n << 14);
    const float4 gx4 = *(const float4*)&g_gx[i4];
    const float4 gy4 = *(const float4*)&g_gy[i4];
    float r[4];
    const float gxs[4] = {gx4.x, gx4.y, gx4.z, gx4.w};
    const float gys[4] = {gy4.x, gy4.y, gy4.z, gy4.w};
    #pragma unroll
    for (int j = 0; j < 4; j++) {
        const float ix = ((gxs[j] + 1.0f) * (float)W_ - 1.0f) * 0.5f;
        const float iy = ((gys[j] + 1.0f) * (float)H_ - 1.0f) * 0.5f;
        const float x0f = floorf(ix);
        const float y0f = floorf(iy);
        const int ix0 = (int)x0f, iy0 = (int)y0f;
        const int ix1 = ix0 + 1, iy1 = iy0 + 1;
        const float wx1 = ix - x0f, wy1 = iy - y0f;
        const float wx0 = 1.0f - wx1, wy0 = 1.0f - wy1;
        float v = 0.0f;
        if ((unsigned)iy0 < H_ && (unsigned)ix0 < W_) v = fmaf(__ldg(&img[iy0 * W_ + ix0]), wy0 * wx0, v);
        if ((unsigned)iy0 < H_ && (unsigned)ix1 < W_) v = fmaf(__ldg(&img[iy0 * W_ + ix1]), wy0 * wx1, v);
        if ((unsigned)iy1 < H_ && (unsigned)ix0 < W_) v = fmaf(__ldg(&img[iy1 * W_ + ix0]), wy1 * wx0, v);
        if ((unsigned)iy1 < H_ && (unsigned)ix1 < W_) v = fmaf(__ldg(&img[iy1 * W_ + ix1]), wy1 * wx1, v);
        r[j] = v;
    }
    *(float4*)&out[i4] = make_float4(r[0], r[1], r[2], r[3]);
}

extern "C" void kernel_launch(void* const* d_in, const int* in_sizes, int n_in,
                              void* d_out, int out_size) {
    const float* x  = (const float*)d_in[0];
    const float* Ws = (const float*)d_in[1];
    const float* bs = (const float*)d_in[2];
    const float* Wx = (const float*)d_in[3];
    const float* bx = (const float*)d_in[4];
    const float* Wy = (const float*)d_in[5];
    const float* by = (const float*)d_in[6];
    float* out = (float*)d_out;

    cudaFuncSetAttribute(conv_mma_kernel,
                         cudaFuncAttributeMaxDynamicSharedMemorySize, SMEM_BYTES);

    split_x_kernel<<<B_ * H_, 256>>>(x);
    prep_w_kernel<<<(9 * NOUT * 64 + 255) / 256, 256>>>(Ws, bs, Wx, bx, Wy, by);
    conv_mma_kernel<<<B_ * H_ * 2, 256, SMEM_BYTES>>>();
    sample_kernel<<<NTOT / 4 / 256, 256>>>(out);
}

// round 15
// speedup vs baseline: 1.2381x; 1.1183x over previous
#include <cuda_runtime.h>
#include <cuda_fp16.h>
#include <cstdint>

#define B_ 16
#define C_ 64
#define H_ 128
#define W_ 128
#define NTOT (B_*C_*H_*W_)
#define NOUT 192
#define WSCALE 16.0f
#define WSCALE_INV 0.0625f

// ---- scratch (allocation-free rule: __device__ globals) ----
__device__ float  g_score[NTOT];
__device__ float  g_gx[NTOT];
__device__ float  g_gy[NTOT];
__device__ __half g_xh16[NTOT];          // NHWC: [b][y][x][ci]
__device__ __half g_xl16[NTOT];
__device__ __half g_B16h[9 * NOUT * 64]; // [tap][n][ci], scaled x16
__device__ __half g_B16l[9 * NOUT * 64];
__device__ float  g_bias[NOUT];

// ---- conv smem layout (halves). M=64 tile -> 2 CTAs/SM ----
#define ARS   72
#define AROWS 66
#define APLN  (AROWS * ARS)               /* 4752 */
#define OFF_AH 0
#define OFF_AL (3 * APLN)                 /* 14256 */
#define OFF_B  (6 * APLN)                 /* 28512 */
#define BTS    (NOUT * ARS)               /* 13824 */
#define SMEM_HALVES (OFF_B + 2 * BTS)     /* 56160 halves = 112320 B */
#define SMEM_BYTES  (SMEM_HALVES * 2)
#define EP_STRIDE 68

__device__ __forceinline__ uint32_t smem_addr(const void* p) {
    return (uint32_t)__cvta_generic_to_shared(p);
}

#define CP_ASYNC16(dst, src) \
    asm volatile("cp.async.cg.shared.global [%0], [%1], 16;" :: "r"(dst), "l"(src) : "memory")
#define CP_ASYNC16Z(dst, src, sz) \
    asm volatile("cp.async.cg.shared.global [%0], [%1], 16, %2;" :: "r"(dst), "l"(src), "r"(sz) : "memory")
#define CP_COMMIT() asm volatile("cp.async.commit_group;" ::: "memory")
#define CP_WAIT0()  asm volatile("cp.async.wait_group 0;" ::: "memory")
#define BAR_PAIR(id) asm volatile("bar.sync %0, 64;" :: "r"(id) : "memory")

__device__ __forceinline__ void ldsm_x4(uint32_t* r, uint32_t addr) {
    asm volatile("ldmatrix.sync.aligned.m8n8.x4.shared.b16 {%0,%1,%2,%3}, [%4];"
        : "=r"(r[0]), "=r"(r[1]), "=r"(r[2]), "=r"(r[3]) : "r"(addr));
}

__device__ __forceinline__ void mma16(float* d, const uint32_t* a, const uint32_t* b) {
    asm volatile(
        "mma.sync.aligned.m16n8k16.row.col.f32.f16.f16.f32 "
        "{%0,%1,%2,%3}, {%4,%5,%6,%7}, {%8,%9}, {%0,%1,%2,%3};"
        : "+f"(d[0]), "+f"(d[1]), "+f"(d[2]), "+f"(d[3])
        : "r"(a[0]), "r"(a[1]), "r"(a[2]), "r"(a[3]), "r"(b[0]), "r"(b[1]));
}

// ---- split x to fp16 h/l and transpose NCHW -> NHWC (vectorized stores) ----
__global__ __launch_bounds__(256)
void split_x_kernel(const float* __restrict__ x) {
    __shared__ float tile[64 * 129];
    const int b = blockIdx.x >> 7;
    const int y = blockIdx.x & 127;
    const int tid = threadIdx.x;

    // read: float4-coalesced, 64 ci-rows x 32 quads
    #pragma unroll
    for (int i = 0; i < 8; i++) {
        const int idx = i * 256 + tid;          // (ci, q)
        const int ci = idx >> 5, q = idx & 31;
        const float4 v = *(const float4*)&x[(((b * 64 + ci) << 7) + y << 7) + q * 4];
        tile[ci * 129 + q * 4 + 0] = v.x;
        tile[ci * 129 + q * 4 + 1] = v.y;
        tile[ci * 129 + q * 4 + 2] = v.z;
        tile[ci * 129 + q * 4 + 3] = v.w;
    }
    __syncthreads();
    // write: thread = (xx, ci4); 4 consecutive ci packed into one 8B store per array
    #pragma unroll
    for (int i = 0; i < 8; i++) {
        const int idx = i * 256 + tid;          // (xx, ci4)
        const int xx = idx >> 4, ci4 = idx & 15;
        __half h[4], l[4];
        #pragma unroll
        for (int j = 0; j < 4; j++) {
            const float v = tile[(ci4 * 4 + j) * 129 + xx];
            h[j] = __float2half(v);
            l[j] = __float2half(v - __half2float(h[j]));
        }
        const int o = (((b << 7) + y << 7) + xx << 6) + ci4 * 4;
        *(uint2*)&g_xh16[o] = *(const uint2*)h;
        *(uint2*)&g_xl16[o] = *(const uint2*)l;
    }
}

// ---- prep weights: [tap][n][ci], scaled x16, fp16 h/l split ----
__global__ __launch_bounds__(256)
void prep_w_kernel(const float* __restrict__ Ws, const float* __restrict__ bs,
                   const float* __restrict__ Wx, const float* __restrict__ bx,
                   const float* __restrict__ Wy, const float* __restrict__ by) {
    const int idx = blockIdx.x * blockDim.x + threadIdx.x;
    if (idx < 9 * NOUT * 64) {
        const int tap = idx / (NOUT * 64);
        const int rem = idx - tap * (NOUT * 64);
        const int n = rem >> 6, ci = rem & 63;
        const int set = n >> 6, co = n & 63;
        const float* Wt = (set == 0) ? Ws : ((set == 1) ? Wx : Wy);
        const float w = Wt[(co * 64 + ci) * 9 + tap] * WSCALE;
        const __half h = __float2half(w);
        g_B16h[idx] = h;
        g_B16l[idx] = __float2half(w - __half2float(h));
    }
    if (idx < NOUT) {
        const int set = idx >> 6, co = idx & 63;
        const float* Bt = (set == 0) ? bs : ((set == 1) ? bx : by);
        g_bias[idx] = Bt[co];
    }
}

// ---- conv GEMM: CTA = (b, y, x-half). M=64, N=192, K=9x64. 2 CTAs/SM ----
// Tap order rotated by blockIdx.x % 9 (de-phases co-resident CTAs).
// B reload per warp-pair with named barriers: 4 independent pipelines per CTA.
__global__ __launch_bounds__(256, 2)
void conv_mma_kernel() {
    extern __shared__ __half smem[];
    float* s_out = (float*)smem;          // aliases A region in epilogue
    const uint32_t sb = smem_addr(smem);
    const int tid = threadIdx.x;
    const int wid = tid >> 5;
    const int lane = tid & 31;
    const int xh = blockIdx.x & 1;
    const int y = (blockIdx.x >> 1) & 127;
    const int b = blockIdx.x >> 8;
    const int x0 = xh << 6;
    const int toff = blockIdx.x % 9;

    const int mbase = (wid >> 2) * 32;    // 2 m-warps x 32
    const int nbase = (wid & 3) * 48;     // 4 n-warps x 48
    const int barid = 1 + (wid & 3);      // named barrier per warp pair
    const int ptid  = ((wid >> 2) << 5) + lane;  // 0..63 within pair

    // ldmatrix lane addressing
    const int a_row16 = lane & 15;
    const int a_kh    = (lane >> 4) * 8;
    const int b_ntp   = (lane >> 4) * 8;
    const int b_kh    = ((lane >> 3) & 1) * 8;
    const int b_row   = lane & 7;

    float acc[2][6][4];
    #pragma unroll
    for (int mt = 0; mt < 2; mt++)
        #pragma unroll
        for (int nt = 0; nt < 6; nt++)
            #pragma unroll
            for (int r = 0; r < 4; r++) acc[mt][nt][r] = 0.0f;

    // ---- prefetch B for first tap (= toff), all threads ----
    {
        const int gbase = toff * NOUT * 64;
        #pragma unroll
        for (int it = 0; it < 6; it++) {
            const int idx = it * 256 + tid;
            const int n = idx >> 3, ci8 = idx & 7;
            const int go = gbase + (n << 6) + ci8 * 8;
            const uint32_t so = sb + (uint32_t)(OFF_B + n * ARS + ci8 * 8) * 2;
            CP_ASYNC16(so,           (const char*)&g_B16h[go]);
            CP_ASYNC16(so + BTS * 2, (const char*)&g_B16l[go]);
        }
    }

    // ---- stage A via cp.async (zero-fill for halo): 3 rows x 66 cols ----
    #pragma unroll
    for (int it = 0; it < 7; it++) {
        const int idx = it * 256 + tid;
        if (idx < 3 * AROWS * 8) {
            const int dy = idx / (AROWS * 8);
            const int rem = idx - dy * (AROWS * 8);
            const int xr = rem >> 3;
            const int ci8 = rem & 7;
            const int y_in = y + dy - 1;
            const int x_in = x0 + xr - 1;
            const bool ok = ((unsigned)y_in < 128u) & ((unsigned)x_in < 128u);
            const int yc = ok ? y_in : 0, xc = ok ? x_in : 0;
            const int o = ((((b << 7) + yc << 7) + xc) << 6) + ci8 * 8;
            const uint32_t sz = ok ? 16u : 0u;
            const uint32_t so = sb + (uint32_t)(OFF_AH + dy * APLN + xr * ARS + ci8 * 8) * 2;
            CP_ASYNC16Z(so,                           (const char*)&g_xh16[o], sz);
            CP_ASYNC16Z(so + (OFF_AL - OFF_AH) * 2,   (const char*)&g_xl16[o], sz);
        }
    }
    CP_COMMIT();
    CP_WAIT0();
    __syncthreads();

    #pragma unroll 1
    for (int t = 0; t < 9; t++) {
        int tap = t + toff; if (tap >= 9) tap -= 9;
        const int dy = tap / 3;
        const int dx = tap - dy * 3;

        const uint32_t aBaseH = sb + (uint32_t)(OFF_AH + dy * APLN
                              + (mbase + a_row16 + dx) * ARS + a_kh) * 2;
        const uint32_t aBaseL = aBaseH + (uint32_t)(OFF_AL - OFF_AH) * 2;
        const uint32_t bBaseH = sb + (uint32_t)(OFF_B
                              + (nbase + b_ntp + b_row) * ARS + b_kh) * 2;
        const uint32_t bBaseL = bBaseH + (uint32_t)(BTS) * 2;

        #pragma unroll
        for (int ks = 0; ks < 4; ks++) {
            const uint32_t ko = (uint32_t)ks * 32;
            uint32_t Ah[2][4], Al[2][4], Bh[3][4], Bl[3][4];
            #pragma unroll
            for (int mt = 0; mt < 2; mt++) {
                ldsm_x4(Ah[mt], aBaseH + (uint32_t)(mt * 16 * ARS) * 2 + ko);
                ldsm_x4(Al[mt], aBaseL + (uint32_t)(mt * 16 * ARS) * 2 + ko);
            }
            #pragma unroll
            for (int p = 0; p < 3; p++) {
                ldsm_x4(Bh[p], bBaseH + (uint32_t)(p * 16 * ARS) * 2 + ko);
                ldsm_x4(Bl[p], bBaseL + (uint32_t)(p * 16 * ARS) * 2 + ko);
            }
            #pragma unroll
            for (int mt = 0; mt < 2; mt++)
                #pragma unroll
                for (int nt = 0; nt < 6; nt++)
                    mma16(acc[mt][nt], Ah[mt], &Bh[nt >> 1][(nt & 1) * 2]);
            #pragma unroll
            for (int mt = 0; mt < 2; mt++)
                #pragma unroll
                for (int nt = 0; nt < 6; nt++)
                    mma16(acc[mt][nt], Ah[mt], &Bl[nt >> 1][(nt & 1) * 2]);
            #pragma unroll
            for (int mt = 0; mt < 2; mt++)
                #pragma unroll
                for (int nt = 0; nt < 6; nt++)
                    mma16(acc[mt][nt], Al[mt], &Bh[nt >> 1][(nt & 1) * 2]);
        }

        // pair-local B slice reload: warps {w, w+4} own rows nbase..nbase+47
        if (t < 8) {
            BAR_PAIR(barid);    // pair done reading its slice
            int tapn = t + 1 + toff; if (tapn >= 9) tapn -= 9;
            const int gbase = tapn * NOUT * 64;
            #pragma unroll
            for (int it = 0; it < 6; it++) {
                const int c = it * 64 + ptid;        // 0..383
                const int r = c >> 3, ci8 = c & 7;   // r 0..47
                const int n = nbase + r;
                const int go = gbase + (n << 6) + ci8 * 8;
                const uint32_t so = sb + (uint32_t)(OFF_B + n * ARS + ci8 * 8) * 2;
                CP_ASYNC16(so,           (const char*)&g_B16h[go]);
                CP_ASYNC16(so + BTS * 2, (const char*)&g_B16l[go]);
            }
            CP_COMMIT();
            CP_WAIT0();
            BAR_PAIR(barid);    // slice visible to both pair warps
        }
    }

    __syncthreads();            // all taps done; A region dead -> alias s_out

    // ---- epilogue: transpose through smem, coalesced float4 stores ----
    const int lr = lane >> 2;
    const int lc = lane & 3;
    #pragma unroll
    for (int nt = 0; nt < 6; nt++) {
        const int n0 = nbase + nt * 8 + 2 * lc;
        #pragma unroll
        for (int mt = 0; mt < 2; mt++) {
            const int m0 = mbase + mt * 16 + lr;
            s_out[n0 * EP_STRIDE + m0]           = acc[mt][nt][0];
            s_out[(n0 + 1) * EP_STRIDE + m0]     = acc[mt][nt][1];
            s_out[n0 * EP_STRIDE + m0 + 8]       = acc[mt][nt][2];
            s_out[(n0 + 1) * EP_STRIDE + m0 + 8] = acc[mt][nt][3];
        }
    }
    __syncthreads();

    // readout: 192 rows x 16 float4, coalesced
    #pragma unroll 1
    for (int it = 0; it < 12; it++) {
        const int idx = it * 256 + tid;
        const int n = idx >> 4;
        const int m4 = idx & 15;
        const int set = n >> 6, co = n & 63;
        float* op = (set == 0) ? g_score : ((set == 1) ? g_gx : g_gy);
        const float bias = __ldg(&g_bias[n]);
        float4 v = *(const float4*)&s_out[n * EP_STRIDE + m4 * 4];
        v.x = fmaf(v.x, WSCALE_INV, bias);
        v.y = fmaf(v.y, WSCALE_INV, bias);
        v.z = fmaf(v.z, WSCALE_INV, bias);
        v.w = fmaf(v.w, WSCALE_INV, bias);
        *(float4*)&op[((b * 64 + co) << 14) + (y << 7) + x0 + m4 * 4] = v;
    }
}

// ---- bilinear grid sample, 4 px/thread (align_corners=False, zeros) ----
__global__ void sample_kernel(float* __restrict__ out) {
    const int i4 = (blockIdx.x * blockDim.x + threadIdx.x) * 4;
    if (i4 >= NTOT) return;
    const int n = i4 >> 14;
    const float* img = g_score + ((size_t)n << 14);
    const float4 gx4 = *(const float4*)&g_gx[i4];
    const float4 gy4 = *(const float4*)&g_gy[i4];
    float r[4];
    const float gxs[4] = {gx4.x, gx4.y, gx4.z, gx4.w};
    const float gys[4] = {gy4.x, gy4.y, gy4.z, gy4.w};
    #pragma unroll
    for (int j = 0; j < 4; j++) {
        const float ix = ((gxs[j] + 1.0f) * (float)W_ - 1.0f) * 0.5f;
        const float iy = ((gys[j] + 1.0f) * (float)H_ - 1.0f) * 0.5f;
        const float x0f = floorf(ix);
        const float y0f = floorf(iy);
        const int ix0 = (int)x0f, iy0 = (int)y0f;
        const int ix1 = ix0 + 1, iy1 = iy0 + 1;
        const float wx1 = ix - x0f, wy1 = iy - y0f;
        const float wx0 = 1.0f - wx1, wy0 = 1.0f - wy1;
        float v = 0.0f;
        if ((unsigned)iy0 < H_ && (unsigned)ix0 < W_) v = fmaf(__ldg(&img[iy0 * W_ + ix0]), wy0 * wx0, v);
        if ((unsigned)iy0 < H_ && (unsigned)ix1 < W_) v = fmaf(__ldg(&img[iy0 * W_ + ix1]), wy0 * wx1, v);
        if ((unsigned)iy1 < H_ && (unsigned)ix0 < W_) v = fmaf(__ldg(&img[iy1 * W_ + ix0]), wy1 * wx0, v);
        if ((unsigned)iy1 < H_ && (unsigned)ix1 < W_) v = fmaf(__ldg(&img[iy1 * W_ + ix1]), wy1 * wx1, v);
        r[j] = v;
    }
    *(float4*)&out[i4] = make_float4(r[0], r[1], r[2], r[3]);
}

extern "C" void kernel_launch(void* const* d_in, const int* in_sizes, int n_in,
                              void* d_out, int out_size) {
    const float* x  = (const float*)d_in[0];
    const float* Ws = (const float*)d_in[1];
    const float* bs = (const float*)d_in[2];
    const float* Wx = (const float*)d_in[3];
    const float* bx = (const float*)d_in[4];
    const float* Wy = (const float*)d_in[5];
    const float* by = (const float*)d_in[6];
    float* out = (float*)d_out;

    cudaFuncSetAttribute(conv_mma_kernel,
                         cudaFuncAttributeMaxDynamicSharedMemorySize, SMEM_BYTES);

    split_x_kernel<<<B_ * H_, 256>>>(x);
    prep_w_kernel<<<(9 * NOUT * 64 + 255) / 256, 256>>>(Ws, bs, Wx, bx, Wy, by);
    conv_mma_kernel<<<B_ * H_ * 2, 256, SMEM_BYTES>>>();
    sample_kernel<<<NTOT / 4 / 256, 256>>>(out);
}

// round 16
// speedup vs baseline: 1.3094x; 1.0576x over previous
#include <cuda_runtime.h>
#include <cuda_fp16.h>
#include <cstdint>

#define B_ 16
#define C_ 64
#define H_ 128
#define W_ 128
#define NTOT (B_*C_*H_*W_)
#define NOUT 192
#define WSCALE 16.0f
#define WSCALE_INV 0.0625f

// ---- scratch (allocation-free rule: __device__ globals) ----
__device__ float  g_score[NTOT];
__device__ float  g_gx[NTOT];
__device__ float  g_gy[NTOT];
__device__ __half g_xh16[NTOT];          // NHWC: [b][y][x][ci]
__device__ __half g_xl16[NTOT];
__device__ __half g_B16h[9 * NOUT * 64]; // [tap][n][ci], scaled x16
__device__ __half g_B16l[9 * NOUT * 64];
__device__ float  g_bias[NOUT];

// ---- conv smem layout (halves). M=64 tile -> 2 CTAs/SM ----
#define ARS   72
#define AROWS 66
#define APLN  (AROWS * ARS)               /* 4752 */
#define OFF_AH 0
#define OFF_AL (3 * APLN)                 /* 14256 */
#define OFF_B  (6 * APLN)                 /* 28512 */
#define BTS    (NOUT * ARS)               /* 13824 */
#define SMEM_HALVES (OFF_B + 2 * BTS)     /* 56160 halves = 112320 B */
#define SMEM_BYTES  (SMEM_HALVES * 2)
#define EP_STRIDE 68

__device__ __forceinline__ uint32_t smem_addr(const void* p) {
    return (uint32_t)__cvta_generic_to_shared(p);
}

#define CP_ASYNC16(dst, src) \
    asm volatile("cp.async.cg.shared.global [%0], [%1], 16;" :: "r"(dst), "l"(src) : "memory")
#define CP_ASYNC16Z(dst, src, sz) \
    asm volatile("cp.async.cg.shared.global [%0], [%1], 16, %2;" :: "r"(dst), "l"(src), "r"(sz) : "memory")
#define CP_COMMIT() asm volatile("cp.async.commit_group;" ::: "memory")
#define CP_WAIT0()  asm volatile("cp.async.wait_group 0;" ::: "memory")
#define BAR_PAIR(id) asm volatile("bar.sync %0, 64;" :: "r"(id) : "memory")

__device__ __forceinline__ void ldsm_x4(uint32_t* r, uint32_t addr) {
    asm volatile("ldmatrix.sync.aligned.m8n8.x4.shared.b16 {%0,%1,%2,%3}, [%4];"
        : "=r"(r[0]), "=r"(r[1]), "=r"(r[2]), "=r"(r[3]) : "r"(addr));
}

__device__ __forceinline__ void mma16(float* d, const uint32_t* a, const uint32_t* b) {
    asm volatile(
        "mma.sync.aligned.m16n8k16.row.col.f32.f16.f16.f32 "
        "{%0,%1,%2,%3}, {%4,%5,%6,%7}, {%8,%9}, {%0,%1,%2,%3};"
        : "+f"(d[0]), "+f"(d[1]), "+f"(d[2]), "+f"(d[3])
        : "r"(a[0]), "r"(a[1]), "r"(a[2]), "r"(a[3]), "r"(b[0]), "r"(b[1]));
}

// ---- split x to fp16 h/l and transpose NCHW -> NHWC (vectorized stores) ----
__global__ __launch_bounds__(256)
void split_x_kernel(const float* __restrict__ x) {
    __shared__ float tile[64 * 129];
    const int b = blockIdx.x >> 7;
    const int y = blockIdx.x & 127;
    const int tid = threadIdx.x;

    #pragma unroll
    for (int i = 0; i < 8; i++) {
        const int idx = i * 256 + tid;
        const int ci = idx >> 5, q = idx & 31;
        const float4 v = *(const float4*)&x[(((b * 64 + ci) << 7) + y << 7) + q * 4];
        tile[ci * 129 + q * 4 + 0] = v.x;
        tile[ci * 129 + q * 4 + 1] = v.y;
        tile[ci * 129 + q * 4 + 2] = v.z;
        tile[ci * 129 + q * 4 + 3] = v.w;
    }
    __syncthreads();
    #pragma unroll
    for (int i = 0; i < 8; i++) {
        const int idx = i * 256 + tid;
        const int xx = idx >> 4, ci4 = idx & 15;
        __half h[4], l[4];
        #pragma unroll
        for (int j = 0; j < 4; j++) {
            const float v = tile[(ci4 * 4 + j) * 129 + xx];
            h[j] = __float2half(v);
            l[j] = __float2half(v - __half2float(h[j]));
        }
        const int o = (((b << 7) + y << 7) + xx << 6) + ci4 * 4;
        *(uint2*)&g_xh16[o] = *(const uint2*)h;
        *(uint2*)&g_xl16[o] = *(const uint2*)l;
    }
}

// ---- prep weights: [tap][n][ci], scaled x16, fp16 h/l split ----
__global__ __launch_bounds__(256)
void prep_w_kernel(const float* __restrict__ Ws, const float* __restrict__ bs,
                   const float* __restrict__ Wx, const float* __restrict__ bx,
                   const float* __restrict__ Wy, const float* __restrict__ by) {
    const int idx = blockIdx.x * blockDim.x + threadIdx.x;
    if (idx < 9 * NOUT * 64) {
        const int tap = idx / (NOUT * 64);
        const int rem = idx - tap * (NOUT * 64);
        const int n = rem >> 6, ci = rem & 63;
        const int set = n >> 6, co = n & 63;
        const float* Wt = (set == 0) ? Ws : ((set == 1) ? Wx : Wy);
        const float w = Wt[(co * 64 + ci) * 9 + tap] * WSCALE;
        const __half h = __float2half(w);
        g_B16h[idx] = h;
        g_B16l[idx] = __float2half(w - __half2float(h));
    }
    if (idx < NOUT) {
        const int set = idx >> 6, co = idx & 63;
        const float* Bt = (set == 0) ? bs : ((set == 1) ? bx : by);
        g_bias[idx] = Bt[co];
    }
}

// ---- conv GEMM: CTA = (b, y, x-half). M=64, N=192, K=9x64. 2 CTAs/SM ----
__global__ __launch_bounds__(256, 2)
void conv_mma_kernel() {
    extern __shared__ __half smem[];
    float* s_out = (float*)smem;          // aliases A region in epilogue
    const uint32_t sb = smem_addr(smem);
    const int tid = threadIdx.x;
    const int wid = tid >> 5;
    const int lane = tid & 31;
    const int xh = blockIdx.x & 1;
    const int y = (blockIdx.x >> 1) & 127;
    const int b = blockIdx.x >> 8;
    const int x0 = xh << 6;
    const int toff = blockIdx.x % 9;

    const int mbase = (wid >> 2) * 32;
    const int nbase = (wid & 3) * 48;
    const int barid = 1 + (wid & 3);
    const int ptid  = ((wid >> 2) << 5) + lane;

    const int a_row16 = lane & 15;
    const int a_kh    = (lane >> 4) * 8;
    const int b_ntp   = (lane >> 4) * 8;
    const int b_kh    = ((lane >> 3) & 1) * 8;
    const int b_row   = lane & 7;

    float acc[2][6][4];
    #pragma unroll
    for (int mt = 0; mt < 2; mt++)
        #pragma unroll
        for (int nt = 0; nt < 6; nt++)
            #pragma unroll
            for (int r = 0; r < 4; r++) acc[mt][nt][r] = 0.0f;

    {
        const int gbase = toff * NOUT * 64;
        #pragma unroll
        for (int it = 0; it < 6; it++) {
            const int idx = it * 256 + tid;
            const int n = idx >> 3, ci8 = idx & 7;
            const int go = gbase + (n << 6) + ci8 * 8;
            const uint32_t so = sb + (uint32_t)(OFF_B + n * ARS + ci8 * 8) * 2;
            CP_ASYNC16(so,           (const char*)&g_B16h[go]);
            CP_ASYNC16(so + BTS * 2, (const char*)&g_B16l[go]);
        }
    }

    #pragma unroll
    for (int it = 0; it < 7; it++) {
        const int idx = it * 256 + tid;
        if (idx < 3 * AROWS * 8) {
            const int dy = idx / (AROWS * 8);
            const int rem = idx - dy * (AROWS * 8);
            const int xr = rem >> 3;
            const int ci8 = rem & 7;
            const int y_in = y + dy - 1;
            const int x_in = x0 + xr - 1;
            const bool ok = ((unsigned)y_in < 128u) & ((unsigned)x_in < 128u);
            const int yc = ok ? y_in : 0, xc = ok ? x_in : 0;
            const int o = ((((b << 7) + yc << 7) + xc) << 6) + ci8 * 8;
            const uint32_t sz = ok ? 16u : 0u;
            const uint32_t so = sb + (uint32_t)(OFF_AH + dy * APLN + xr * ARS + ci8 * 8) * 2;
            CP_ASYNC16Z(so,                           (const char*)&g_xh16[o], sz);
            CP_ASYNC16Z(so + (OFF_AL - OFF_AH) * 2,   (const char*)&g_xl16[o], sz);
        }
    }
    CP_COMMIT();
    CP_WAIT0();
    __syncthreads();

    #pragma unroll 1
    for (int t = 0; t < 9; t++) {
        int tap = t + toff; if (tap >= 9) tap -= 9;
        const int dy = tap / 3;
        const int dx = tap - dy * 3;

        const uint32_t aBaseH = sb + (uint32_t)(OFF_AH + dy * APLN
                              + (mbase + a_row16 + dx) * ARS + a_kh) * 2;
        const uint32_t aBaseL = aBaseH + (uint32_t)(OFF_AL - OFF_AH) * 2;
        const uint32_t bBaseH = sb + (uint32_t)(OFF_B
                              + (nbase + b_ntp + b_row) * ARS + b_kh) * 2;
        const uint32_t bBaseL = bBaseH + (uint32_t)(BTS) * 2;

        #pragma unroll
        for (int ks = 0; ks < 4; ks++) {
            const uint32_t ko = (uint32_t)ks * 32;
            uint32_t Ah[2][4], Al[2][4], Bh[3][4], Bl[3][4];
            #pragma unroll
            for (int mt = 0; mt < 2; mt++) {
                ldsm_x4(Ah[mt], aBaseH + (uint32_t)(mt * 16 * ARS) * 2 + ko);
                ldsm_x4(Al[mt], aBaseL + (uint32_t)(mt * 16 * ARS) * 2 + ko);
            }
            #pragma unroll
            for (int p = 0; p < 3; p++) {
                ldsm_x4(Bh[p], bBaseH + (uint32_t)(p * 16 * ARS) * 2 + ko);
                ldsm_x4(Bl[p], bBaseL + (uint32_t)(p * 16 * ARS) * 2 + ko);
            }
            #pragma unroll
            for (int mt = 0; mt < 2; mt++)
                #pragma unroll
                for (int nt = 0; nt < 6; nt++)
                    mma16(acc[mt][nt], Ah[mt], &Bh[nt >> 1][(nt & 1) * 2]);
            #pragma unroll
            for (int mt = 0; mt < 2; mt++)
                #pragma unroll
                for (int nt = 0; nt < 6; nt++)
                    mma16(acc[mt][nt], Ah[mt], &Bl[nt >> 1][(nt & 1) * 2]);
            #pragma unroll
            for (int mt = 0; mt < 2; mt++)
                #pragma unroll
                for (int nt = 0; nt < 6; nt++)
                    mma16(acc[mt][nt], Al[mt], &Bh[nt >> 1][(nt & 1) * 2]);
        }

        if (t < 8) {
            BAR_PAIR(barid);
            int tapn = t + 1 + toff; if (tapn >= 9) tapn -= 9;
            const int gbase = tapn * NOUT * 64;
            #pragma unroll
            for (int it = 0; it < 6; it++) {
                const int c = it * 64 + ptid;
                const int r = c >> 3, ci8 = c & 7;
                const int n = nbase + r;
                const int go = gbase + (n << 6) + ci8 * 8;
                const uint32_t so = sb + (uint32_t)(OFF_B + n * ARS + ci8 * 8) * 2;
                CP_ASYNC16(so,           (const char*)&g_B16h[go]);
                CP_ASYNC16(so + BTS * 2, (const char*)&g_B16l[go]);
            }
            CP_COMMIT();
            CP_WAIT0();
            BAR_PAIR(barid);
        }
    }

    __syncthreads();

    const int lr = lane >> 2;
    const int lc = lane & 3;
    #pragma unroll
    for (int nt = 0; nt < 6; nt++) {
        const int n0 = nbase + nt * 8 + 2 * lc;
        #pragma unroll
        for (int mt = 0; mt < 2; mt++) {
            const int m0 = mbase + mt * 16 + lr;
            s_out[n0 * EP_STRIDE + m0]           = acc[mt][nt][0];
            s_out[(n0 + 1) * EP_STRIDE + m0]     = acc[mt][nt][1];
            s_out[n0 * EP_STRIDE + m0 + 8]       = acc[mt][nt][2];
            s_out[(n0 + 1) * EP_STRIDE + m0 + 8] = acc[mt][nt][3];
        }
    }
    __syncthreads();

    #pragma unroll 1
    for (int it = 0; it < 12; it++) {
        const int idx = it * 256 + tid;
        const int n = idx >> 4;
        const int m4 = idx & 15;
        const int set = n >> 6, co = n & 63;
        float* op = (set == 0) ? g_score : ((set == 1) ? g_gx : g_gy);
        const float bias = __ldg(&g_bias[n]);
        float4 v = *(const float4*)&s_out[n * EP_STRIDE + m4 * 4];
        v.x = fmaf(v.x, WSCALE_INV, bias);
        v.y = fmaf(v.y, WSCALE_INV, bias);
        v.z = fmaf(v.z, WSCALE_INV, bias);
        v.w = fmaf(v.w, WSCALE_INV, bias);
        *(float4*)&op[((b * 64 + co) << 14) + (y << 7) + x0 + m4 * 4] = v;
    }
}

// ---- bilinear grid sample: one CTA per (b,c) image, 1024 thr, 16 px/thr ----
// Keeps each CTA's gather working set = its own 64 KB score image (L1-resident).
__global__ __launch_bounds__(1024, 2)
void sample_kernel(float* __restrict__ out) {
    const int n = blockIdx.x;             // image index 0..1023
    const int tid = threadIdx.x;
    const float* img = g_score + ((size_t)n << 14);
    const int base = n << 14;

    #pragma unroll
    for (int q = 0; q < 4; q++) {
        const int i4 = base + ((q << 10) + tid) * 4;
        const float4 gx4 = *(const float4*)&g_gx[i4];
        const float4 gy4 = *(const float4*)&g_gy[i4];
        float r[4];
        const float gxs[4] = {gx4.x, gx4.y, gx4.z, gx4.w};
        const float gys[4] = {gy4.x, gy4.y, gy4.z, gy4.w};
        #pragma unroll
        for (int j = 0; j < 4; j++) {
            const float ix = ((gxs[j] + 1.0f) * (float)W_ - 1.0f) * 0.5f;
            const float iy = ((gys[j] + 1.0f) * (float)H_ - 1.0f) * 0.5f;
            const float x0f = floorf(ix);
            const float y0f = floorf(iy);
            const int ix0 = (int)x0f, iy0 = (int)y0f;
            const int ix1 = ix0 + 1, iy1 = iy0 + 1;
            const float wx1 = ix - x0f, wy1 = iy - y0f;
            const float wx0 = 1.0f - wx1, wy0 = 1.0f - wy1;
            float v = 0.0f;
            if ((unsigned)iy0 < H_ && (unsigned)ix0 < W_) v = fmaf(__ldg(&img[iy0 * W_ + ix0]), wy0 * wx0, v);
            if ((unsigned)iy0 < H_ && (unsigned)ix1 < W_) v = fmaf(__ldg(&img[iy0 * W_ + ix1]), wy0 * wx1, v);
            if ((unsigned)iy1 < H_ && (unsigned)ix0 < W_) v = fmaf(__ldg(&img[iy1 * W_ + ix0]), wy1 * wx0, v);
            if ((unsigned)iy1 < H_ && (unsigned)ix1 < W_) v = fmaf(__ldg(&img[iy1 * W_ + ix1]), wy1 * wx1, v);
            r[j] = v;
        }
        *(float4*)&out[i4] = make_float4(r[0], r[1], r[2], r[3]);
    }
}

extern "C" void kernel_launch(void* const* d_in, const int* in_sizes, int n_in,
                              void* d_out, int out_size) {
    const float* x  = (const float*)d_in[0];
    const float* Ws = (const float*)d_in[1];
    const float* bs = (const float*)d_in[2];
    const float* Wx = (const float*)d_in[3];
    const float* bx = (const float*)d_in[4];
    const float* Wy = (const float*)d_in[5];
    const float* by = (const float*)d_in[6];
    float* out = (float*)d_out;

    cudaFuncSetAttribute(conv_mma_kernel,
                         cudaFuncAttributeMaxDynamicSharedMemorySize, SMEM_BYTES);

    split_x_kernel<<<B_ * H_, 256>>>(x);
    prep_w_kernel<<<(9 * NOUT * 64 + 255) / 256, 256>>>(Ws, bs, Wx, bx, Wy, by);
    conv_mma_kernel<<<B_ * H_ * 2, 256, SMEM_BYTES>>>();
    sample_kernel<<<B_ * C_, 1024>>>(out);
}

// round 17
// speedup vs baseline: 1.3164x; 1.0053x over previous
#include <cuda_runtime.h>
#include <cuda_fp16.h>
#include <cstdint>

#define B_ 16
#define C_ 64
#define H_ 128
#define W_ 128
#define NTOT (B_*C_*H_*W_)
#define NOUT 192
#define WSCALE 16.0f
#define WSCALE_INV 0.0625f

// ---- scratch (allocation-free rule: __device__ globals) ----
__device__ float  g_score[NTOT];
__device__ float  g_gx[NTOT];
__device__ float  g_gy[NTOT];
__device__ __half g_xh16[NTOT];          // NHWC: [b][y][x][ci]
__device__ __half g_xl16[NTOT];
__device__ __half g_B16h[9 * NOUT * 64]; // [tap][n][ci], scaled x16
__device__ __half g_B16l[9 * NOUT * 64];
__device__ float  g_bias[NOUT];

// ---- conv smem layout (halves). M=64 tile -> 2 CTAs/SM ----
#define ARS   72
#define AROWS 66
#define APLN  (AROWS * ARS)               /* 4752 */
#define OFF_AH 0
#define OFF_AL (3 * APLN)                 /* 14256 */
#define OFF_B  (6 * APLN)                 /* 28512 */
#define BTS    (NOUT * ARS)               /* 13824 */
#define SMEM_HALVES (OFF_B + 2 * BTS)     /* 56160 halves = 112320 B */
#define SMEM_BYTES  (SMEM_HALVES * 2)
#define EP_STRIDE 68

__device__ __forceinline__ uint32_t smem_addr(const void* p) {
    return (uint32_t)__cvta_generic_to_shared(p);
}

#define CP_ASYNC16(dst, src) \
    asm volatile("cp.async.cg.shared.global [%0], [%1], 16;" :: "r"(dst), "l"(src) : "memory")
#define CP_ASYNC16Z(dst, src, sz) \
    asm volatile("cp.async.cg.shared.global [%0], [%1], 16, %2;" :: "r"(dst), "l"(src), "r"(sz) : "memory")
#define CP_COMMIT() asm volatile("cp.async.commit_group;" ::: "memory")
#define CP_WAIT0()  asm volatile("cp.async.wait_group 0;" ::: "memory")
#define BAR_PAIR(id) asm volatile("bar.sync %0, 64;" :: "r"(id) : "memory")

__device__ __forceinline__ void ldsm_x4(uint32_t* r, uint32_t addr) {
    asm volatile("ldmatrix.sync.aligned.m8n8.x4.shared.b16 {%0,%1,%2,%3}, [%4];"
        : "=r"(r[0]), "=r"(r[1]), "=r"(r[2]), "=r"(r[3]) : "r"(addr));
}

__device__ __forceinline__ void mma16(float* d, const uint32_t* a, const uint32_t* b) {
    asm volatile(
        "mma.sync.aligned.m16n8k16.row.col.f32.f16.f16.f32 "
        "{%0,%1,%2,%3}, {%4,%5,%6,%7}, {%8,%9}, {%0,%1,%2,%3};"
        : "+f"(d[0]), "+f"(d[1]), "+f"(d[2]), "+f"(d[3])
        : "r"(a[0]), "r"(a[1]), "r"(a[2]), "r"(a[3]), "r"(b[0]), "r"(b[1]));
}

// ---- fused prep: blocks [0,2048) split x; blocks [2048, 2048+432) prep weights ----
__global__ __launch_bounds__(256)
void prep_kernel(const float* __restrict__ x,
                 const float* __restrict__ Ws, const float* __restrict__ bs,
                 const float* __restrict__ Wx, const float* __restrict__ bx,
                 const float* __restrict__ Wy, const float* __restrict__ by) {
    __shared__ float tile[64 * 129];
    const int tid = threadIdx.x;

    if (blockIdx.x < 2048) {
        // ---- split x to fp16 h/l and transpose NCHW -> NHWC ----
        const int b = blockIdx.x >> 7;
        const int y = blockIdx.x & 127;

        #pragma unroll
        for (int i = 0; i < 8; i++) {
            const int idx = i * 256 + tid;
            const int ci = idx >> 5, q = idx & 31;
            const float4 v = *(const float4*)&x[(((b * 64 + ci) << 7) + y << 7) + q * 4];
            tile[ci * 129 + q * 4 + 0] = v.x;
            tile[ci * 129 + q * 4 + 1] = v.y;
            tile[ci * 129 + q * 4 + 2] = v.z;
            tile[ci * 129 + q * 4 + 3] = v.w;
        }
        __syncthreads();
        #pragma unroll
        for (int i = 0; i < 8; i++) {
            const int idx = i * 256 + tid;
            const int xx = idx >> 4, ci4 = idx & 15;
            __half h[4], l[4];
            #pragma unroll
            for (int j = 0; j < 4; j++) {
                const float v = tile[(ci4 * 4 + j) * 129 + xx];
                h[j] = __float2half(v);
                l[j] = __float2half(v - __half2float(h[j]));
            }
            const int o = (((b << 7) + y << 7) + xx << 6) + ci4 * 4;
            *(uint2*)&g_xh16[o] = *(const uint2*)h;
            *(uint2*)&g_xl16[o] = *(const uint2*)l;
        }
    } else {
        // ---- prep weights: [tap][n][ci], scaled x16, fp16 h/l split ----
        const int idx = (blockIdx.x - 2048) * 256 + tid;
        if (idx < 9 * NOUT * 64) {
            const int tap = idx / (NOUT * 64);
            const int rem = idx - tap * (NOUT * 64);
            const int n = rem >> 6, ci = rem & 63;
            const int set = n >> 6, co = n & 63;
            const float* Wt = (set == 0) ? Ws : ((set == 1) ? Wx : Wy);
            const float w = Wt[(co * 64 + ci) * 9 + tap] * WSCALE;
            const __half h = __float2half(w);
            g_B16h[idx] = h;
            g_B16l[idx] = __float2half(w - __half2float(h));
        }
        if (idx < NOUT) {
            const int set = idx >> 6, co = idx & 63;
            const float* Bt = (set == 0) ? bs : ((set == 1) ? bx : by);
            g_bias[idx] = Bt[co];
        }
    }
}

// ---- conv GEMM: CTA = (b, y, x-half). M=64, N=192, K=9x64. 2 CTAs/SM ----
__global__ __launch_bounds__(256, 2)
void conv_mma_kernel() {
    extern __shared__ __half smem[];
    float* s_out = (float*)smem;          // aliases A region in epilogue
    const uint32_t sb = smem_addr(smem);
    const int tid = threadIdx.x;
    const int wid = tid >> 5;
    const int lane = tid & 31;
    const int xh = blockIdx.x & 1;
    const int y = (blockIdx.x >> 1) & 127;
    const int b = blockIdx.x >> 8;
    const int x0 = xh << 6;
    const int toff = blockIdx.x % 9;

    const int mbase = (wid >> 2) * 32;
    const int nbase = (wid & 3) * 48;
    const int barid = 1 + (wid & 3);
    const int ptid  = ((wid >> 2) << 5) + lane;

    const int a_row16 = lane & 15;
    const int a_kh    = (lane >> 4) * 8;
    const int b_ntp   = (lane >> 4) * 8;
    const int b_kh    = ((lane >> 3) & 1) * 8;
    const int b_row   = lane & 7;

    float acc[2][6][4];
    #pragma unroll
    for (int mt = 0; mt < 2; mt++)
        #pragma unroll
        for (int nt = 0; nt < 6; nt++)
            #pragma unroll
            for (int r = 0; r < 4; r++) acc[mt][nt][r] = 0.0f;

    {
        const int gbase = toff * NOUT * 64;
        #pragma unroll
        for (int it = 0; it < 6; it++) {
            const int idx = it * 256 + tid;
            const int n = idx >> 3, ci8 = idx & 7;
            const int go = gbase + (n << 6) + ci8 * 8;
            const uint32_t so = sb + (uint32_t)(OFF_B + n * ARS + ci8 * 8) * 2;
            CP_ASYNC16(so,           (const char*)&g_B16h[go]);
            CP_ASYNC16(so + BTS * 2, (const char*)&g_B16l[go]);
        }
    }

    #pragma unroll
    for (int it = 0; it < 7; it++) {
        const int idx = it * 256 + tid;
        if (idx < 3 * AROWS * 8) {
            const int dy = idx / (AROWS * 8);
            const int rem = idx - dy * (AROWS * 8);
            const int xr = rem >> 3;
            const int ci8 = rem & 7;
            const int y_in = y + dy - 1;
            const int x_in = x0 + xr - 1;
            const bool ok = ((unsigned)y_in < 128u) & ((unsigned)x_in < 128u);
            const int yc = ok ? y_in : 0, xc = ok ? x_in : 0;
            const int o = ((((b << 7) + yc << 7) + xc) << 6) + ci8 * 8;
            const uint32_t sz = ok ? 16u : 0u;
            const uint32_t so = sb + (uint32_t)(OFF_AH + dy * APLN + xr * ARS + ci8 * 8) * 2;
            CP_ASYNC16Z(so,                           (const char*)&g_xh16[o], sz);
            CP_ASYNC16Z(so + (OFF_AL - OFF_AH) * 2,   (const char*)&g_xl16[o], sz);
        }
    }
    CP_COMMIT();
    CP_WAIT0();
    __syncthreads();

    #pragma unroll 1
    for (int t = 0; t < 9; t++) {
        int tap = t + toff; if (tap >= 9) tap -= 9;
        const int dy = tap / 3;
        const int dx = tap - dy * 3;

        const uint32_t aBaseH = sb + (uint32_t)(OFF_AH + dy * APLN
                              + (mbase + a_row16 + dx) * ARS + a_kh) * 2;
        const uint32_t aBaseL = aBaseH + (uint32_t)(OFF_AL - OFF_AH) * 2;
        const uint32_t bBaseH = sb + (uint32_t)(OFF_B
                              + (nbase + b_ntp + b_row) * ARS + b_kh) * 2;
        const uint32_t bBaseL = bBaseH + (uint32_t)(BTS) * 2;

        #pragma unroll
        for (int ks = 0; ks < 4; ks++) {
            const uint32_t ko = (uint32_t)ks * 32;
            uint32_t Ah[2][4], Al[2][4], Bh[3][4], Bl[3][4];
            #pragma unroll
            for (int mt = 0; mt < 2; mt++) {
                ldsm_x4(Ah[mt], aBaseH + (uint32_t)(mt * 16 * ARS) * 2 + ko);
                ldsm_x4(Al[mt], aBaseL + (uint32_t)(mt * 16 * ARS) * 2 + ko);
            }
            #pragma unroll
            for (int p = 0; p < 3; p++) {
                ldsm_x4(Bh[p], bBaseH + (uint32_t)(p * 16 * ARS) * 2 + ko);
                ldsm_x4(Bl[p], bBaseL + (uint32_t)(p * 16 * ARS) * 2 + ko);
            }
            #pragma unroll
            for (int mt = 0; mt < 2; mt++)
                #pragma unroll
                for (int nt = 0; nt < 6; nt++)
                    mma16(acc[mt][nt], Ah[mt], &Bh[nt >> 1][(nt & 1) * 2]);
            #pragma unroll
            for (int mt = 0; mt < 2; mt++)
                #pragma unroll
                for (int nt = 0; nt < 6; nt++)
                    mma16(acc[mt][nt], Ah[mt], &Bl[nt >> 1][(nt & 1) * 2]);
            #pragma unroll
            for (int mt = 0; mt < 2; mt++)
                #pragma unroll
                for (int nt = 0; nt < 6; nt++)
                    mma16(acc[mt][nt], Al[mt], &Bh[nt >> 1][(nt & 1) * 2]);
        }

        if (t < 8) {
            BAR_PAIR(barid);
            int tapn = t + 1 + toff; if (tapn >= 9) tapn -= 9;
            const int gbase = tapn * NOUT * 64;
            #pragma unroll
            for (int it = 0; it < 6; it++) {
                const int c = it * 64 + ptid;
                const int r = c >> 3, ci8 = c & 7;
                const int n = nbase + r;
                const int go = gbase + (n << 6) + ci8 * 8;
                const uint32_t so = sb + (uint32_t)(OFF_B + n * ARS + ci8 * 8) * 2;
                CP_ASYNC16(so,           (const char*)&g_B16h[go]);
                CP_ASYNC16(so + BTS * 2, (const char*)&g_B16l[go]);
            }
            CP_COMMIT();
            CP_WAIT0();
            BAR_PAIR(barid);
        }
    }

    __syncthreads();

    const int lr = lane >> 2;
    const int lc = lane & 3;
    #pragma unroll
    for (int nt = 0; nt < 6; nt++) {
        const int n0 = nbase + nt * 8 + 2 * lc;
        #pragma unroll
        for (int mt = 0; mt < 2; mt++) {
            const int m0 = mbase + mt * 16 + lr;
            s_out[n0 * EP_STRIDE + m0]           = acc[mt][nt][0];
            s_out[(n0 + 1) * EP_STRIDE + m0]     = acc[mt][nt][1];
            s_out[n0 * EP_STRIDE + m0 + 8]       = acc[mt][nt][2];
            s_out[(n0 + 1) * EP_STRIDE + m0 + 8] = acc[mt][nt][3];
        }
    }
    __syncthreads();

    #pragma unroll 1
    for (int it = 0; it < 12; it++) {
        const int idx = it * 256 + tid;
        const int n = idx >> 4;
        const int m4 = idx & 15;
        const int set = n >> 6, co = n & 63;
        float* op = (set == 0) ? g_score : ((set == 1) ? g_gx : g_gy);
        const float bias = __ldg(&g_bias[n]);
        float4 v = *(const float4*)&s_out[n * EP_STRIDE + m4 * 4];
        v.x = fmaf(v.x, WSCALE_INV, bias);
        v.y = fmaf(v.y, WSCALE_INV, bias);
        v.z = fmaf(v.z, WSCALE_INV, bias);
        v.w = fmaf(v.w, WSCALE_INV, bias);
        *(float4*)&op[((b * 64 + co) << 14) + (y << 7) + x0 + m4 * 4] = v;
    }
}

// ---- bilinear grid sample: one CTA per (b,c) image, 1024 thr, 16 px/thr ----
// gx/gy streamed with evict-first hint; out with streaming store; score reads
// keep default caching so the 64 KB image stays L1/L2-resident.
__global__ __launch_bounds__(1024, 2)
void sample_kernel(float* __restrict__ out) {
    const int n = blockIdx.x;             // image index 0..1023
    const int tid = threadIdx.x;
    const float* img = g_score + ((size_t)n << 14);
    const int base = n << 14;

    #pragma unroll
    for (int q = 0; q < 4; q++) {
        const int i4 = base + ((q << 10) + tid) * 4;
        const float4 gx4 = __ldcs((const float4*)&g_gx[i4]);
        const float4 gy4 = __ldcs((const float4*)&g_gy[i4]);
        float r[4];
        const float gxs[4] = {gx4.x, gx4.y, gx4.z, gx4.w};
        const float gys[4] = {gy4.x, gy4.y, gy4.z, gy4.w};
        #pragma unroll
        for (int j = 0; j < 4; j++) {
            const float ix = ((gxs[j] + 1.0f) * (float)W_ - 1.0f) * 0.5f;
            const float iy = ((gys[j] + 1.0f) * (float)H_ - 1.0f) * 0.5f;
            const float x0f = floorf(ix);
            const float y0f = floorf(iy);
            const int ix0 = (int)x0f, iy0 = (int)y0f;
            const int ix1 = ix0 + 1, iy1 = iy0 + 1;
            const float wx1 = ix - x0f, wy1 = iy - y0f;
            const float wx0 = 1.0f - wx1, wy0 = 1.0f - wy1;
            float v = 0.0f;
            if ((unsigned)iy0 < H_ && (unsigned)ix0 < W_) v = fmaf(__ldg(&img[iy0 * W_ + ix0]), wy0 * wx0, v);
            if ((unsigned)iy0 < H_ && (unsigned)ix1 < W_) v = fmaf(__ldg(&img[iy0 * W_ + ix1]), wy0 * wx1, v);
            if ((unsigned)iy1 < H_ && (unsigned)ix0 < W_) v = fmaf(__ldg(&img[iy1 * W_ + ix0]), wy1 * wx0, v);
            if ((unsigned)iy1 < H_ && (unsigned)ix1 < W_) v = fmaf(__ldg(&img[iy1 * W_ + ix1]), wy1 * wx1, v);
            r[j] = v;
        }
        __stcs((float4*)&out[i4], make_float4(r[0], r[1], r[2], r[3]));
    }
}

extern "C" void kernel_launch(void* const* d_in, const int* in_sizes, int n_in,
                              void* d_out, int out_size) {
    const float* x  = (const float*)d_in[0];
    const float* Ws = (const float*)d_in[1];
    const float* bs = (const float*)d_in[2];
    const float* Wx = (const float*)d_in[3];
    const float* bx = (const float*)d_in[4];
    const float* Wy = (const float*)d_in[5];
    const float* by = (const float*)d_in[6];
    float* out = (float*)d_out;

    cudaFuncSetAttribute(conv_mma_kernel,
                         cudaFuncAttributeMaxDynamicSharedMemorySize, SMEM_BYTES);

    prep_kernel<<<2048 + 432, 256>>>(x, Ws, bs, Wx, bx, Wy, by);
    conv_mma_kernel<<<B_ * H_ * 2, 256, SMEM_BYTES>>>();
    sample_kernel<<<B_ * C_, 1024>>>(out);
}